// round 5
// baseline (speedup 1.0000x reference)
#include <cuda_runtime.h>
#include <cuda_bf16.h>
#include <math_constants.h>
#include <cstdint>

#define BATCH 4
#define SEQ   2048
#define DM    1024

#define BM 128
#define BN 128
#define BK 64                       // int8 per chunk (64 bytes per row)
#define STAGES 4
#define MAT_BYTES (128 * 64)        // one 128x64 s8 matrix = 8192 B
#define STAGE_BYTES (4 * MAT_BYTES)         // Ah, Al, Bh, Bl = 32768 B
#define SMEM_TOTAL (STAGES * STAGE_BYTES)   // 131072 B

// ---------------------------------------------------------------------------
// Scratch (allocation-free)
// ---------------------------------------------------------------------------
__device__ signed char g_xh[(size_t)BATCH*SEQ*DM];
__device__ signed char g_xl[(size_t)BATCH*SEQ*DM];
__device__ float       g_sx[(size_t)BATCH*SEQ];
__device__ signed char g_wh[(size_t)3*DM*DM];
__device__ signed char g_wl[(size_t)3*DM*DM];
__device__ float       g_sw[(size_t)3*DM];
__device__ float       g_QKVf[(size_t)3*BATCH*SEQ*DM];   // fp32 Q,K,V
__device__ signed char g_qkh[(size_t)2*BATCH*SEQ*DM];    // Q,K int8 hi
__device__ signed char g_qkl[(size_t)2*BATCH*SEQ*DM];
__device__ float       g_sqk[(size_t)2*BATCH*SEQ];
__device__ float       g_Vtf[(size_t)BATCH*DM*SEQ];      // fp32 V^T
__device__ signed char g_vth[(size_t)BATCH*DM*SEQ];
__device__ signed char g_vtl[(size_t)BATCH*DM*SEQ];
__device__ float       g_sv[(size_t)BATCH*DM];
__device__ float       g_Pf[(size_t)BATCH*SEQ*SEQ];      // fp32 scores
__device__ signed char g_ph[(size_t)BATCH*SEQ*SEQ];
__device__ signed char g_pl[(size_t)BATCH*SEQ*SEQ];
__device__ float       g_sp[(size_t)BATCH*SEQ];

// ---------------------------------------------------------------------------
// PTX helpers (base sm_80+ features only)
// ---------------------------------------------------------------------------
__device__ __forceinline__ uint32_t smem_u32(const void* p) {
    uint32_t a;
    asm("{ .reg .u64 t; cvta.to.shared.u64 t, %1; cvt.u32.u64 %0, t; }" : "=r"(a) : "l"(p));
    return a;
}
__device__ __forceinline__ void cp_async16(uint32_t s, const void* g) {
    asm volatile("cp.async.cg.shared.global [%0], [%1], 16;" :: "r"(s), "l"(g));
}
#define CP_COMMIT() asm volatile("cp.async.commit_group;" ::: "memory")
#define CP_WAIT2()  asm volatile("cp.async.wait_group 2;" ::: "memory")
#define CP_WAIT0()  asm volatile("cp.async.wait_group 0;" ::: "memory")

__device__ __forceinline__ void ldmx4(uint32_t& r0, uint32_t& r1, uint32_t& r2, uint32_t& r3,
                                      uint32_t a) {
    asm volatile("ldmatrix.sync.aligned.m8n8.x4.shared.b16 {%0,%1,%2,%3}, [%4];"
        : "=r"(r0), "=r"(r1), "=r"(r2), "=r"(r3) : "r"(a));
}
__device__ __forceinline__ void ldmx2(uint32_t& r0, uint32_t& r1, uint32_t a) {
    asm volatile("ldmatrix.sync.aligned.m8n8.x2.shared.b16 {%0,%1}, [%2];"
        : "=r"(r0), "=r"(r1) : "r"(a));
}
// s8 IMMA, k=32, s32 accumulate
__device__ __forceinline__ void imma(int* c, const uint32_t* a, const uint32_t* b) {
    asm volatile("mma.sync.aligned.m16n8k32.row.col.s32.s8.s8.s32 "
        "{%0,%1,%2,%3}, {%4,%5,%6,%7}, {%8,%9}, {%0,%1,%2,%3};"
        : "+r"(c[0]), "+r"(c[1]), "+r"(c[2]), "+r"(c[3])
        : "r"(a[0]), "r"(a[1]), "r"(a[2]), "r"(a[3]), "r"(b[0]), "r"(b[1]));
}

// Swizzled smem byte offset for (row, 16B-chunk c16) inside a 128x64-s8 tile.
__device__ __forceinline__ uint32_t sw_off(int row, int c16) {
    return (uint32_t)(row * 64 + ((c16 ^ ((row >> 1) & 3)) << 4));
}

// ---------------------------------------------------------------------------
// int8 dual-word NT GEMM:
//   C[m,n] = alpha * sA[m] * sB[n] * ( accA + accB/128 )
//   accA = sum Ah*Bh,  accB = sum (Ah*Bl + Al*Bh)   (exact s32 accumulation)
// ---------------------------------------------------------------------------
__global__ __launch_bounds__(256, 1) void gemm_i8(
    const signed char* __restrict__ Ah, const signed char* __restrict__ Al,
    const signed char* __restrict__ Bh, const signed char* __restrict__ Bl,
    const float* __restrict__ scA, const float* __restrict__ scB,
    float* __restrict__ out,
    int lda, int ldb, int ldc,
    long sA, long sB, long sC, long sScA, long sScB,
    float alpha, int Ktot, int causalSkip, int causalK)
{
    const int m0 = blockIdx.y * BM;
    const int n0 = blockIdx.x * BN;
    if (causalSkip && n0 >= m0 + BM) return;

    extern __shared__ char smem[];
    const uint32_t sb = smem_u32(smem);

    const int tid  = threadIdx.x;
    const int lane = tid & 31;
    const int wid  = tid >> 5;
    const int warpM0 = (wid >> 2) * 64;   // 2 warps along M
    const int warpN0 = (wid & 3) * 32;    // 4 warps along N

    Ah += (size_t)blockIdx.z * sA;  Al += (size_t)blockIdx.z * sA;
    Bh += (size_t)blockIdx.z * sB;  Bl += (size_t)blockIdx.z * sB;

    const int kEnd = causalK ? min(Ktot, m0 + BM) : Ktot;
    const int nCh = kEnd / BK;

    int gr[2], gc[2];
#pragma unroll
    for (int r = 0; r < 2; r++) {
        int i = tid + r * 256;
        gr[r] = i >> 2;
        gc[r] = i & 3;
    }

    auto issue = [&](int c) {
        const uint32_t st = sb + (uint32_t)(c & (STAGES - 1)) * STAGE_BYTES;
        const int k0 = c * BK;
#pragma unroll
        for (int r = 0; r < 2; r++) {
            const int row = gr[r], c16 = gc[r];
            const uint32_t so = sw_off(row, c16);
            const size_t ao = (size_t)(m0 + row) * lda + k0 + c16 * 16;
            const size_t bo = (size_t)(n0 + row) * ldb + k0 + c16 * 16;
            cp_async16(st + so,                 Ah + ao);
            cp_async16(st + MAT_BYTES + so,     Al + ao);
            cp_async16(st + 2 * MAT_BYTES + so, Bh + bo);
            cp_async16(st + 3 * MAT_BYTES + so, Bl + bo);
        }
    };

    int accA[4][4][4], accB[4][4][4];
#pragma unroll
    for (int i = 0; i < 4; i++)
#pragma unroll
        for (int j = 0; j < 4; j++)
#pragma unroll
            for (int k = 0; k < 4; k++) { accA[i][j][k] = 0; accB[i][j][k] = 0; }

#pragma unroll
    for (int s = 0; s < STAGES - 1; s++) {
        if (s < nCh) issue(s);
        CP_COMMIT();
    }

    const int aRow = (lane & 15);
    const int aHi  = (lane >> 4);
    const int bRow = (lane & 7);
    const int bHi  = ((lane >> 3) & 1);

    for (int c = 0; c < nCh; c++) {
        CP_WAIT2();
        __syncthreads();
        if (c + STAGES - 1 < nCh) issue(c + STAGES - 1);
        CP_COMMIT();

        const uint32_t st = sb + (uint32_t)(c & (STAGES - 1)) * STAGE_BYTES;
#pragma unroll
        for (int ks = 0; ks < 2; ks++) {    // two k32 halves per 64-chunk
            uint32_t ah[4][4], al[4][4], bh[4][2], bl[4][2];
#pragma unroll
            for (int mf = 0; mf < 4; mf++) {
                const int row = warpM0 + mf * 16 + aRow;
                const uint32_t so = sw_off(row, ks * 2 + aHi);
                ldmx4(ah[mf][0], ah[mf][1], ah[mf][2], ah[mf][3], st + so);
                ldmx4(al[mf][0], al[mf][1], al[mf][2], al[mf][3], st + MAT_BYTES + so);
            }
#pragma unroll
            for (int nf = 0; nf < 4; nf++) {
                const int row = warpN0 + nf * 8 + bRow;
                const uint32_t so = sw_off(row, ks * 2 + bHi);
                ldmx2(bh[nf][0], bh[nf][1], st + 2 * MAT_BYTES + so);
                ldmx2(bl[nf][0], bl[nf][1], st + 3 * MAT_BYTES + so);
            }
#pragma unroll
            for (int mf = 0; mf < 4; mf++)
#pragma unroll
                for (int nf = 0; nf < 4; nf++) {
                    imma(accA[mf][nf], ah[mf], bh[nf]);
                    imma(accB[mf][nf], ah[mf], bl[nf]);
                    imma(accB[mf][nf], al[mf], bh[nf]);
                }
        }
        __syncthreads();
    }
    CP_WAIT0();

    // epilogue: combine + scales
    const long cb = (long)blockIdx.z * sC;
    const float* sAr = scA + (size_t)blockIdx.z * sScA;
    const float* sBr = scB + (size_t)blockIdx.z * sScB;
    const int rBase = m0 + warpM0 + (lane >> 2);
    const int cBase = n0 + warpN0 + (lane & 3) * 2;
#pragma unroll
    for (int mf = 0; mf < 4; mf++) {
#pragma unroll
        for (int h = 0; h < 2; h++) {
            const int row = rBase + mf * 16 + h * 8;
            const float rs = __ldg(sAr + row) * alpha;
#pragma unroll
            for (int nf = 0; nf < 4; nf++) {
                const int col = cBase + nf * 8;
                const float c0 = __ldg(sBr + col);
                const float c1 = __ldg(sBr + col + 1);
                float v0 = ((float)accA[mf][nf][2*h]   + (float)accB[mf][nf][2*h]   * 0.0078125f) * rs * c0;
                float v1 = ((float)accA[mf][nf][2*h+1] + (float)accB[mf][nf][2*h+1] * 0.0078125f) * rs * c1;
                *(float2*)(out + cb + (size_t)row * ldc + col) = make_float2(v0, v1);
            }
        }
    }
}

// ---------------------------------------------------------------------------
// Per-row dual int8 quantization: x = s*(h + l/128), s = rowmax/126.
// ---------------------------------------------------------------------------
__global__ __launch_bounds__(256) void quantize_rows(
    const float* __restrict__ src, signed char* __restrict__ h8,
    signed char* __restrict__ l8, float* __restrict__ sc, int L)
{
    const int row = blockIdx.x;
    const float* r = src + (size_t)row * L;
    const int tid = threadIdx.x;
    const int n = L >> 8;          // 4 or 8

    __shared__ float sred[8];
    __shared__ float sbc;

    float v[8];
    float mx = 0.f;
#pragma unroll 8
    for (int i = 0; i < n; i++) {
        v[i] = r[tid + i * 256];
        mx = fmaxf(mx, fabsf(v[i]));
    }
#pragma unroll
    for (int o = 16; o; o >>= 1) mx = fmaxf(mx, __shfl_xor_sync(0xffffffffu, mx, o));
    if ((tid & 31) == 0) sred[tid >> 5] = mx;
    __syncthreads();
    if (tid == 0) {
        float t = sred[0];
#pragma unroll
        for (int w = 1; w < 8; w++) t = fmaxf(t, sred[w]);
        sbc = (t > 0.f) ? t : 1.f;
    }
    __syncthreads();
    const float s = sbc / 126.f;
    const float is = 126.f / sbc;
#pragma unroll 8
    for (int i = 0; i < n; i++) {
        float t = v[i] * is;
        float vh = rintf(t);
        float vl = rintf((t - vh) * 128.f);
        h8[(size_t)row * L + tid + i * 256] = (signed char)(int)vh;
        l8[(size_t)row * L + tid + i * 256] = (signed char)(int)vl;
    }
    if (tid == 0) sc[row] = s;
}

// fp32 transpose: [B][SEQ][DM] -> [B][DM][SEQ]
__global__ __launch_bounds__(256) void transpose_f32(
    const float* __restrict__ src, float* __restrict__ dst)
{
    __shared__ float t[32][33];
    const int b  = blockIdx.z;
    const int d0 = blockIdx.x * 32;
    const int s0 = blockIdx.y * 32;
    const int tx = threadIdx.x & 31, ty = threadIdx.x >> 5;

    const float* S_ = src + ((size_t)b * SEQ + s0) * DM + d0;
#pragma unroll
    for (int i = 0; i < 4; i++)
        t[ty + i * 8][tx] = S_[(size_t)(ty + i * 8) * DM + tx];
    __syncthreads();
    float* D_ = dst + ((size_t)b * DM + d0) * SEQ + s0;
#pragma unroll
    for (int i = 0; i < 4; i++)
        D_[(size_t)(ty + i * 8) * SEQ + tx] = t[tx][ty + i * 8];
}

// Causal softmax: fp32 scores in; int8 dual-word P out + per-row scale.
// p = sp*(ph + pl/128), sp = 1/(126*sum). Zero-fills to the 128-boundary.
__global__ __launch_bounds__(256) void softmax_causal(
    const float* __restrict__ P, signed char* __restrict__ Ph,
    signed char* __restrict__ Pl, float* __restrict__ Sp)
{
    const int q = blockIdx.x, b = blockIdx.y;
    const float* row = P + ((size_t)b * SEQ + q) * SEQ;
    signed char* hr = Ph + ((size_t)b * SEQ + q) * SEQ;
    signed char* lr = Pl + ((size_t)b * SEQ + q) * SEQ;
    const int len = q + 1, tid = threadIdx.x;

    __shared__ float sred[8];
    __shared__ float sbc;

    float vals[8]; int n = 0;
    float m = -CUDART_INF_F;
    for (int i = tid; i < len; i += 256) { float v = row[i]; vals[n++] = v; m = fmaxf(m, v); }
#pragma unroll
    for (int o = 16; o; o >>= 1) m = fmaxf(m, __shfl_xor_sync(0xffffffffu, m, o));
    if ((tid & 31) == 0) sred[tid >> 5] = m;
    __syncthreads();
    if (tid == 0) {
        float t = sred[0];
#pragma unroll
        for (int w = 1; w < 8; w++) t = fmaxf(t, sred[w]);
        sbc = t;
    }
    __syncthreads();
    m = sbc;

    float s = 0.f;
#pragma unroll
    for (int k = 0; k < 8; k++)
        if (k < n) { float e = expf(vals[k] - m); vals[k] = e; s += e; }
#pragma unroll
    for (int o = 16; o; o >>= 1) s += __shfl_xor_sync(0xffffffffu, s, o);
    __syncthreads();
    if ((tid & 31) == 0) sred[tid >> 5] = s;
    __syncthreads();
    if (tid == 0) {
        float t = 0.f;
#pragma unroll
        for (int w = 0; w < 8; w++) t += sred[w];
        sbc = t;
    }
    __syncthreads();
    const float sum = sbc;

    // quantize: t = 126*e  (e in (0,1]; row max of e is exactly 1)
    n = 0;
    for (int i = tid; i < len; i += 256) {
        float t = 126.f * vals[n++];
        float vh = rintf(t);
        float vl = rintf((t - vh) * 128.f);
        hr[i] = (signed char)(int)vh;
        lr[i] = (signed char)(int)vl;
    }
    const int tileEnd = ((q >> 7) + 1) << 7;
    for (int i = len + tid; i < tileEnd; i += 256) { hr[i] = 0; lr[i] = 0; }
    if (tid == 0) Sp[(size_t)b * SEQ + q] = 1.f / (126.f * sum);
}

// ---------------------------------------------------------------------------
extern "C" void kernel_launch(void* const* d_in, const int* in_sizes, int n_in,
                              void* d_out, int out_size)
{
    const float* x  = (const float*)d_in[0];
    const float* Wq = (const float*)d_in[1];
    const float* Wk = (const float*)d_in[2];
    const float* Wv = (const float*)d_in[3];
    float* out = (float*)d_out;

    signed char *xh, *xl, *wh, *wl, *qkh, *qkl, *vth, *vtl, *ph, *pl;
    float *sx, *sw, *sqk, *sv, *sp, *QKVf, *Vtf, *Pf;
    cudaGetSymbolAddress((void**)&xh, g_xh);   cudaGetSymbolAddress((void**)&xl, g_xl);
    cudaGetSymbolAddress((void**)&sx, g_sx);
    cudaGetSymbolAddress((void**)&wh, g_wh);   cudaGetSymbolAddress((void**)&wl, g_wl);
    cudaGetSymbolAddress((void**)&sw, g_sw);
    cudaGetSymbolAddress((void**)&QKVf, g_QKVf);
    cudaGetSymbolAddress((void**)&qkh, g_qkh); cudaGetSymbolAddress((void**)&qkl, g_qkl);
    cudaGetSymbolAddress((void**)&sqk, g_sqk);
    cudaGetSymbolAddress((void**)&Vtf, g_Vtf);
    cudaGetSymbolAddress((void**)&vth, g_vth); cudaGetSymbolAddress((void**)&vtl, g_vtl);
    cudaGetSymbolAddress((void**)&sv, g_sv);
    cudaGetSymbolAddress((void**)&Pf, g_Pf);
    cudaGetSymbolAddress((void**)&ph, g_ph);   cudaGetSymbolAddress((void**)&pl, g_pl);
    cudaGetSymbolAddress((void**)&sp, g_sp);

    const long BSD = (long)BATCH * SEQ * DM;
    const long SD  = (long)SEQ * DM;
    const long SS  = (long)SEQ * SEQ;

    cudaFuncSetAttribute(gemm_i8, cudaFuncAttributeMaxDynamicSharedMemorySize, SMEM_TOTAL);

    // 1) quantize inputs
    quantize_rows<<<BATCH * SEQ, 256>>>(x, xh, xl, sx, DM);
    quantize_rows<<<DM, 256>>>(Wq, wh,                wl,                sw,          DM);
    quantize_rows<<<DM, 256>>>(Wk, wh + (long)DM*DM,  wl + (long)DM*DM,  sw + DM,     DM);
    quantize_rows<<<DM, 256>>>(Wv, wh + 2L*DM*DM,     wl + 2L*DM*DM,     sw + 2*DM,   DM);

    // 2) fused QKV projection -> fp32 QKV (z selects weight + output section)
    {
        dim3 g(DM / BN, (BATCH * SEQ) / BM, 3);
        gemm_i8<<<g, 256, SMEM_TOTAL>>>(xh, xl, wh, wl, sx, sw,
            QKVf, DM, DM, DM,
            0, (long)DM * DM, BSD, 0, DM,
            1.f, DM, 0, 0);
    }

    // 3) quantize Q,K rows (d-major, length DM)
    quantize_rows<<<2 * BATCH * SEQ, 256>>>(QKVf, qkh, qkl, sqk, DM);

    // 4) transpose V, quantize V^T rows (length SEQ)
    {
        dim3 g(DM / 32, SEQ / 32, BATCH);
        transpose_f32<<<g, 256>>>(QKVf + 2 * BSD, Vtf);
    }
    quantize_rows<<<BATCH * DM, 256>>>(Vtf, vth, vtl, sv, SEQ);

    // 5) scores: P = (1/32) Q @ K^T (causal tile skip)
    {
        dim3 g(SEQ / BN, SEQ / BM, BATCH);
        gemm_i8<<<g, 256, SMEM_TOTAL>>>(qkh, qkl, qkh + BSD, qkl + BSD,
            sqk, sqk + BATCH * SEQ,
            Pf, DM, DM, SEQ,
            SD, SD, SS, SEQ, SEQ,
            0.03125f, DM, 1, 0);
    }

    // 6) causal softmax -> int8 dual-word P (+ zero fill to 128-boundary)
    softmax_causal<<<dim3(SEQ, BATCH), 256>>>(Pf, ph, pl, sp);

    // 7) O = P @ V  (B operand = V^T, K-major over S; K truncated at diagonal)
    {
        dim3 g(DM / BN, SEQ / BM, BATCH);
        gemm_i8<<<g, 256, SMEM_TOTAL>>>(ph, pl, vth, vtl,
            sp, sv,
            out, SEQ, SEQ, DM,
            SS, SD, SD, SEQ, DM,
            1.f, SEQ, 0, 1);
    }
}

// round 6
// speedup vs baseline: 2.6663x; 2.6663x over previous
#include <cuda_runtime.h>
#include <cuda_bf16.h>
#include <math_constants.h>
#include <cstdint>

#define BATCH 4
#define SEQ   2048
#define DM    1024

#define BM 128
#define BN 128
#define BK 32                      // bf16 per chunk (64 bytes per row)
#define STAGES 3
#define MAT_BYTES (128 * 64)       // one 128x32 bf16 matrix = 8192 B
#define STAGE_BYTES (4 * MAT_BYTES)        // Ahi, Alo, Bhi, Blo = 32768 B
#define SMEM_TOTAL (STAGES * STAGE_BYTES)  // 98304 B

// ---------------------------------------------------------------------------
// Scratch (allocation-free)
// ---------------------------------------------------------------------------
__device__ __nv_bfloat16 g_xhi[(size_t)BATCH*SEQ*DM];
__device__ __nv_bfloat16 g_xlo[(size_t)BATCH*SEQ*DM];
__device__ __nv_bfloat16 g_Whi[(size_t)3*DM*DM];
__device__ __nv_bfloat16 g_Wlo[(size_t)3*DM*DM];
__device__ __nv_bfloat16 g_QKVhi[(size_t)3*BATCH*SEQ*DM];
__device__ __nv_bfloat16 g_QKVlo[(size_t)3*BATCH*SEQ*DM];
__device__ __nv_bfloat16 g_Vthi[(size_t)BATCH*DM*SEQ];
__device__ __nv_bfloat16 g_Vtlo[(size_t)BATCH*DM*SEQ];
__device__ float         g_P  [(size_t)BATCH*SEQ*SEQ];
__device__ __nv_bfloat16 g_Phi[(size_t)BATCH*SEQ*SEQ];
__device__ __nv_bfloat16 g_Plo[(size_t)BATCH*SEQ*SEQ];

// ---------------------------------------------------------------------------
// PTX helpers (base sm_80+ features only)
// ---------------------------------------------------------------------------
__device__ __forceinline__ uint32_t smem_u32(const void* p) {
    uint32_t a;
    asm("{ .reg .u64 t; cvta.to.shared.u64 t, %1; cvt.u32.u64 %0, t; }" : "=r"(a) : "l"(p));
    return a;
}
__device__ __forceinline__ void cp_async16(uint32_t s, const void* g) {
    asm volatile("cp.async.cg.shared.global [%0], [%1], 16;" :: "r"(s), "l"(g));
}
#define CP_COMMIT() asm volatile("cp.async.commit_group;" ::: "memory")
#define CP_WAIT1()  asm volatile("cp.async.wait_group 1;" ::: "memory")

__device__ __forceinline__ void ldmx4(uint32_t& r0, uint32_t& r1, uint32_t& r2, uint32_t& r3,
                                      uint32_t a) {
    asm volatile("ldmatrix.sync.aligned.m8n8.x4.shared.b16 {%0,%1,%2,%3}, [%4];"
        : "=r"(r0), "=r"(r1), "=r"(r2), "=r"(r3) : "r"(a));
}
__device__ __forceinline__ void mma16816(float* c, const uint32_t* a, const uint32_t* b) {
    asm volatile("mma.sync.aligned.m16n8k16.row.col.f32.bf16.bf16.f32 "
        "{%0,%1,%2,%3}, {%4,%5,%6,%7}, {%8,%9}, {%0,%1,%2,%3};"
        : "+f"(c[0]), "+f"(c[1]), "+f"(c[2]), "+f"(c[3])
        : "r"(a[0]), "r"(a[1]), "r"(a[2]), "r"(a[3]), "r"(b[0]), "r"(b[1]));
}

// Swizzled smem byte offset for (row, 16B-chunk c16) inside a 128x32-bf16 tile.
__device__ __forceinline__ uint32_t sw_off(int row, int c16) {
    return (uint32_t)(row * 64 + ((c16 ^ ((row >> 1) & 3)) << 4));
}

// ---------------------------------------------------------------------------
// bf16x3 NT GEMM via mma.sync:
//   C[128,128] tile = (Ahi+Alo)[M,K] @ (Bhi+Blo)[N,K]^T, fp32 accumulate.
// ---------------------------------------------------------------------------
__global__ __launch_bounds__(256, 1) void gemm_mma(
    const __nv_bfloat16* __restrict__ Ahi, const __nv_bfloat16* __restrict__ Alo,
    const __nv_bfloat16* __restrict__ Bhi, const __nv_bfloat16* __restrict__ Blo,
    float* __restrict__ outF,
    __nv_bfloat16* __restrict__ outHi, __nv_bfloat16* __restrict__ outLo,
    int lda, int ldb, int ldc, long sA, long sB, long sC,
    float alpha, int Ktot, int causalSkip, int causalK)
{
    const int m0 = blockIdx.y * BM;
    const int n0 = blockIdx.x * BN;
    if (causalSkip && n0 >= m0 + BM) return;

    extern __shared__ char smem[];
    const uint32_t sb = smem_u32(smem);

    const int tid  = threadIdx.x;
    const int lane = tid & 31;
    const int wid  = tid >> 5;
    const int warpM0 = (wid >> 2) * 64;   // 2 warps along M
    const int warpN0 = (wid & 3) * 32;    // 4 warps along N

    Ahi += (size_t)blockIdx.z * sA;  Alo += (size_t)blockIdx.z * sA;
    Bhi += (size_t)blockIdx.z * sB;  Blo += (size_t)blockIdx.z * sB;

    const int kEnd = causalK ? min(Ktot, m0 + BM) : Ktot;
    const int nCh = kEnd / BK;

    int gr[2], gc[2];
#pragma unroll
    for (int r = 0; r < 2; r++) {
        int i = tid + r * 256;
        gr[r] = i >> 2;
        gc[r] = i & 3;
    }

    auto issue = [&](int c) {
        const uint32_t st = sb + (uint32_t)(c % STAGES) * STAGE_BYTES;
        const int k0 = c * BK;
#pragma unroll
        for (int r = 0; r < 2; r++) {
            const int row = gr[r], c16 = gc[r];
            const uint32_t so = sw_off(row, c16);
            const size_t ao = (size_t)(m0 + row) * lda + k0 + c16 * 8;
            const size_t bo = (size_t)(n0 + row) * ldb + k0 + c16 * 8;
            cp_async16(st + so,                 Ahi + ao);
            cp_async16(st + MAT_BYTES + so,     Alo + ao);
            cp_async16(st + 2 * MAT_BYTES + so, Bhi + bo);
            cp_async16(st + 3 * MAT_BYTES + so, Blo + bo);
        }
    };

    float acc[4][4][4];
#pragma unroll
    for (int i = 0; i < 4; i++)
#pragma unroll
        for (int j = 0; j < 4; j++)
#pragma unroll
            for (int k = 0; k < 4; k++) acc[i][j][k] = 0.f;

    // prologue: 2 stages in flight
    if (0 < nCh) issue(0);
    CP_COMMIT();
    if (1 < nCh) issue(1);
    CP_COMMIT();

    // lane-invariant address pieces
    const int aRow = (lane & 15);             // A: 16 rows x 2 k-halves
    const int aHi  = (lane >> 4);
    const int bRow = (lane & 7) + ((lane >> 4) << 3);   // B pair: nf / nf+1
    const int bHi  = ((lane >> 3) & 1);                 // k-half select

    for (int c = 0; c < nCh; c++) {
        CP_WAIT1();                 // stage c complete
        __syncthreads();            // everyone done reading buffer (c+2)%3
        if (c + 2 < nCh) issue(c + 2);
        CP_COMMIT();

        const uint32_t st = sb + (uint32_t)(c % STAGES) * STAGE_BYTES;
#pragma unroll
        for (int ks = 0; ks < 2; ks++) {
            uint32_t ah[4][4], al[4][4];
#pragma unroll
            for (int mf = 0; mf < 4; mf++) {
                const int row = warpM0 + mf * 16 + aRow;
                const uint32_t so = sw_off(row, ks * 2 + aHi);
                ldmx4(ah[mf][0], ah[mf][1], ah[mf][2], ah[mf][3], st + so);
                ldmx4(al[mf][0], al[mf][1], al[mf][2], al[mf][3], st + MAT_BYTES + so);
            }
#pragma unroll
            for (int nfp = 0; nfp < 2; nfp++) {  // pairs of n-fragments via x4
                const int row = warpN0 + nfp * 16 + bRow;
                const uint32_t so = sw_off(row, ks * 2 + bHi);
                uint32_t bh[4], bl[4];
                ldmx4(bh[0], bh[1], bh[2], bh[3], st + 2 * MAT_BYTES + so);
                ldmx4(bl[0], bl[1], bl[2], bl[3], st + 3 * MAT_BYTES + so);
#pragma unroll
                for (int mf = 0; mf < 4; mf++) {
                    mma16816(acc[mf][2*nfp],     ah[mf], bh + 0);
                    mma16816(acc[mf][2*nfp],     ah[mf], bl + 0);
                    mma16816(acc[mf][2*nfp],     al[mf], bh + 0);
                    mma16816(acc[mf][2*nfp + 1], ah[mf], bh + 2);
                    mma16816(acc[mf][2*nfp + 1], ah[mf], bl + 2);
                    mma16816(acc[mf][2*nfp + 1], al[mf], bh + 2);
                }
            }
        }
    }

    // epilogue
    const long cb = (long)blockIdx.z * sC;
    const int rBase = m0 + warpM0 + (lane >> 2);
    const int cBase = n0 + warpN0 + (lane & 3) * 2;
#pragma unroll
    for (int mf = 0; mf < 4; mf++) {
#pragma unroll
        for (int nf = 0; nf < 4; nf++) {
            const int col = cBase + nf * 8;
#pragma unroll
            for (int h = 0; h < 2; h++) {
                const int row = rBase + mf * 16 + h * 8;
                const float v0 = acc[mf][nf][2 * h];
                const float v1 = acc[mf][nf][2 * h + 1];
                if (outF) {
                    *(float2*)(outF + cb + (size_t)row * ldc + col) =
                        make_float2(v0 * alpha, v1 * alpha);
                } else {
                    __nv_bfloat16 h0 = __float2bfloat16(v0);
                    __nv_bfloat16 h1 = __float2bfloat16(v1);
                    __nv_bfloat16 l0 = __float2bfloat16(v0 - __bfloat162float(h0));
                    __nv_bfloat16 l1 = __float2bfloat16(v1 - __bfloat162float(h1));
                    *(__nv_bfloat162*)(outHi + cb + (size_t)row * ldc + col) =
                        __halves2bfloat162(h0, h1);
                    *(__nv_bfloat162*)(outLo + cb + (size_t)row * ldc + col) =
                        __halves2bfloat162(l0, l1);
                }
            }
        }
    }
}

// ---------------------------------------------------------------------------
__global__ __launch_bounds__(256) void split_hi_lo(
    const float* __restrict__ src, __nv_bfloat16* __restrict__ hi,
    __nv_bfloat16* __restrict__ lo, int n4)
{
    int i = blockIdx.x * 256 + threadIdx.x;
    if (i >= n4) return;
    float4 v = ((const float4*)src)[i];
    __nv_bfloat16 h0 = __float2bfloat16(v.x), h1 = __float2bfloat16(v.y);
    __nv_bfloat16 h2 = __float2bfloat16(v.z), h3 = __float2bfloat16(v.w);
    __nv_bfloat16 l0 = __float2bfloat16(v.x - __bfloat162float(h0));
    __nv_bfloat16 l1 = __float2bfloat16(v.y - __bfloat162float(h1));
    __nv_bfloat16 l2 = __float2bfloat16(v.z - __bfloat162float(h2));
    __nv_bfloat16 l3 = __float2bfloat16(v.w - __bfloat162float(h3));
    __nv_bfloat162* H = (__nv_bfloat162*)hi + 2 * (size_t)i;
    __nv_bfloat162* L = (__nv_bfloat162*)lo + 2 * (size_t)i;
    H[0] = __halves2bfloat162(h0, h1); H[1] = __halves2bfloat162(h2, h3);
    L[0] = __halves2bfloat162(l0, l1); L[1] = __halves2bfloat162(l2, l3);
}

// src [B][SEQ][DM] -> dst [B][DM][SEQ]
__global__ __launch_bounds__(256) void transpose_bf16(
    const __nv_bfloat16* __restrict__ src, __nv_bfloat16* __restrict__ dst)
{
    __shared__ __nv_bfloat16 t[64][65];
    const int b  = blockIdx.z;
    const int n0 = blockIdx.x * 64;
    const int k0 = blockIdx.y * 64;
    const int tx = threadIdx.x & 31, ty = threadIdx.x >> 5;

    const __nv_bfloat16* s = src + ((size_t)b * SEQ + k0) * DM + n0;
#pragma unroll
    for (int i = 0; i < 8; i++) {
        int r = ty + i * 8;
        __nv_bfloat162 v = *(const __nv_bfloat162*)(s + (size_t)r * DM + 2 * tx);
        t[r][2*tx] = v.x; t[r][2*tx+1] = v.y;
    }
    __syncthreads();
    __nv_bfloat16* d = dst + ((size_t)b * DM + n0) * SEQ + k0;
#pragma unroll
    for (int i = 0; i < 8; i++) {
        int rn = ty + i * 8;
        *(__nv_bfloat162*)(d + (size_t)rn * SEQ + 2 * tx) =
            __halves2bfloat162(t[2*tx][rn], t[2*tx+1][rn]);
    }
}

// Causal softmax: fp32 in, bf16 hi/lo out, zero-fill to the 128-boundary.
__global__ __launch_bounds__(256) void softmax_causal(
    const float* __restrict__ P, __nv_bfloat16* __restrict__ Phi,
    __nv_bfloat16* __restrict__ Plo)
{
    const int q = blockIdx.x, b = blockIdx.y;
    const float* row = P + ((size_t)b * SEQ + q) * SEQ;
    __nv_bfloat16* hr = Phi + ((size_t)b * SEQ + q) * SEQ;
    __nv_bfloat16* lr = Plo + ((size_t)b * SEQ + q) * SEQ;
    const int len = q + 1, tid = threadIdx.x;

    __shared__ float sred[8];
    __shared__ float sbc;

    float vals[8]; int n = 0;
    float m = -CUDART_INF_F;
    for (int i = tid; i < len; i += 256) { float v = row[i]; vals[n++] = v; m = fmaxf(m, v); }
#pragma unroll
    for (int o = 16; o; o >>= 1) m = fmaxf(m, __shfl_xor_sync(0xffffffffu, m, o));
    if ((tid & 31) == 0) sred[tid >> 5] = m;
    __syncthreads();
    if (tid == 0) {
        float t = sred[0];
#pragma unroll
        for (int w = 1; w < 8; w++) t = fmaxf(t, sred[w]);
        sbc = t;
    }
    __syncthreads();
    m = sbc;

    float s = 0.f;
#pragma unroll
    for (int k = 0; k < 8; k++)
        if (k < n) { float e = expf(vals[k] - m); vals[k] = e; s += e; }
#pragma unroll
    for (int o = 16; o; o >>= 1) s += __shfl_xor_sync(0xffffffffu, s, o);
    __syncthreads();
    if ((tid & 31) == 0) sred[tid >> 5] = s;
    __syncthreads();
    if (tid == 0) {
        float t = 0.f;
#pragma unroll
        for (int w = 0; w < 8; w++) t += sred[w];
        sbc = 1.f / t;
    }
    __syncthreads();
    const float inv = sbc;

    n = 0;
    for (int i = tid; i < len; i += 256) {
        float e = vals[n++] * inv;
        __nv_bfloat16 h = __float2bfloat16(e);
        hr[i] = h;
        lr[i] = __float2bfloat16(e - __bfloat162float(h));
    }
    const __nv_bfloat16 z = __float2bfloat16(0.f);
    const int tileEnd = ((q >> 7) + 1) << 7;
    for (int i = len + tid; i < tileEnd; i += 256) { hr[i] = z; lr[i] = z; }
}

// ---------------------------------------------------------------------------
extern "C" void kernel_launch(void* const* d_in, const int* in_sizes, int n_in,
                              void* d_out, int out_size)
{
    const float* x  = (const float*)d_in[0];
    const float* Wq = (const float*)d_in[1];
    const float* Wk = (const float*)d_in[2];
    const float* Wv = (const float*)d_in[3];
    float* out = (float*)d_out;

    __nv_bfloat16 *xhi, *xlo, *Whi, *Wlo, *QKVhi, *QKVlo, *Vthi, *Vtlo, *Phi, *Plo;
    float* P;
    cudaGetSymbolAddress((void**)&xhi, g_xhi);     cudaGetSymbolAddress((void**)&xlo, g_xlo);
    cudaGetSymbolAddress((void**)&Whi, g_Whi);     cudaGetSymbolAddress((void**)&Wlo, g_Wlo);
    cudaGetSymbolAddress((void**)&QKVhi, g_QKVhi); cudaGetSymbolAddress((void**)&QKVlo, g_QKVlo);
    cudaGetSymbolAddress((void**)&Vthi, g_Vthi);   cudaGetSymbolAddress((void**)&Vtlo, g_Vtlo);
    cudaGetSymbolAddress((void**)&P, g_P);
    cudaGetSymbolAddress((void**)&Phi, g_Phi);     cudaGetSymbolAddress((void**)&Plo, g_Plo);

    const long BSD = (long)BATCH * SEQ * DM;
    const long SD  = (long)SEQ * DM;
    const long SS  = (long)SEQ * SEQ;

    cudaFuncSetAttribute(gemm_mma, cudaFuncAttributeMaxDynamicSharedMemorySize, SMEM_TOTAL);

    // 1) hi/lo splits
    split_hi_lo<<<(BATCH*SEQ*DM/4 + 255)/256, 256>>>(x, xhi, xlo, BATCH*SEQ*DM/4);
    split_hi_lo<<<(DM*DM/4 + 255)/256, 256>>>(Wq, Whi,            Wlo,            DM*DM/4);
    split_hi_lo<<<(DM*DM/4 + 255)/256, 256>>>(Wk, Whi + (long)DM*DM,   Wlo + (long)DM*DM,   DM*DM/4);
    split_hi_lo<<<(DM*DM/4 + 255)/256, 256>>>(Wv, Whi + 2L*DM*DM, Wlo + 2L*DM*DM, DM*DM/4);

    // 2) Fused QKV projection (z selects weight + output section; A fixed)
    {
        dim3 g(DM / BN, (BATCH * SEQ) / BM, 3);
        gemm_mma<<<g, 256, SMEM_TOTAL>>>(xhi, xlo, Whi, Wlo,
            nullptr, QKVhi, QKVlo,
            DM, DM, DM, 0, (long)DM * DM, BSD,
            1.f, DM, 0, 0);
    }

    // 3) V transpose: [B][S][DM] -> [B][DM][S]
    {
        dim3 g(DM / 64, SEQ / 64, BATCH);
        transpose_bf16<<<g, 256>>>(QKVhi + 2 * BSD, Vthi);
        transpose_bf16<<<g, 256>>>(QKVlo + 2 * BSD, Vtlo);
    }

    // 4) Scores: P = (1/32) Q @ K^T (causal tile skip)
    {
        dim3 g(SEQ / BN, SEQ / BM, BATCH);
        gemm_mma<<<g, 256, SMEM_TOTAL>>>(QKVhi, QKVlo, QKVhi + BSD, QKVlo + BSD,
            P, nullptr, nullptr,
            DM, DM, SEQ, SD, SD, SS,
            0.03125f, DM, 1, 0);
    }

    // 5) Causal softmax -> bf16 hi/lo P (+ zero fill to 128-boundary)
    softmax_causal<<<dim3(SEQ, BATCH), 256>>>(P, Phi, Plo);

    // 6) O = P @ V   (B operand = V^T, K-major over S; K truncated at diag)
    {
        dim3 g(DM / BN, SEQ / BM, BATCH);
        gemm_mma<<<g, 256, SMEM_TOTAL>>>(Phi, Plo, Vthi, Vtlo,
            out, nullptr, nullptr,
            SEQ, SEQ, DM, SS, SD, SD,
            1.f, SEQ, 0, 1);
    }
}

// round 7
// speedup vs baseline: 5.5985x; 2.0997x over previous
#include <cuda_runtime.h>
#include <cuda_fp16.h>
#include <math_constants.h>
#include <cstdint>

#define BATCH 4
#define SEQ   2048
#define DM    1024

#define BM 128
#define BN 128
#define BK 32                      // fp16 per chunk (64 bytes per row)
#define STAGES 3
#define MAT_BYTES (128 * 64)       // one 128x32 fp16 matrix = 8192 B
#define STAGE_BYTES (2 * MAT_BYTES)        // A, B = 16384 B
#define SMEM_TOTAL (STAGES * STAGE_BYTES)  // 49152 B

// ---------------------------------------------------------------------------
// Scratch (allocation-free)
// ---------------------------------------------------------------------------
__device__ __half g_x16[(size_t)BATCH*SEQ*DM];
__device__ __half g_W16[(size_t)3*DM*DM];
__device__ __half g_QKV16[(size_t)3*BATCH*SEQ*DM];
__device__ __half g_Vt16[(size_t)BATCH*DM*SEQ];
__device__ float  g_Pf [(size_t)BATCH*SEQ*SEQ];
__device__ __half g_P16[(size_t)BATCH*SEQ*SEQ];

// ---------------------------------------------------------------------------
// PTX helpers (base sm_80+ features only)
// ---------------------------------------------------------------------------
__device__ __forceinline__ uint32_t smem_u32(const void* p) {
    uint32_t a;
    asm("{ .reg .u64 t; cvta.to.shared.u64 t, %1; cvt.u32.u64 %0, t; }" : "=r"(a) : "l"(p));
    return a;
}
__device__ __forceinline__ void cp_async16(uint32_t s, const void* g) {
    asm volatile("cp.async.cg.shared.global [%0], [%1], 16;" :: "r"(s), "l"(g));
}
#define CP_COMMIT() asm volatile("cp.async.commit_group;" ::: "memory")
#define CP_WAIT1()  asm volatile("cp.async.wait_group 1;" ::: "memory")

__device__ __forceinline__ void ldmx4(uint32_t& r0, uint32_t& r1, uint32_t& r2, uint32_t& r3,
                                      uint32_t a) {
    asm volatile("ldmatrix.sync.aligned.m8n8.x4.shared.b16 {%0,%1,%2,%3}, [%4];"
        : "=r"(r0), "=r"(r1), "=r"(r2), "=r"(r3) : "r"(a));
}
__device__ __forceinline__ void mma16816(float* c, const uint32_t* a, const uint32_t* b) {
    asm volatile("mma.sync.aligned.m16n8k16.row.col.f32.f16.f16.f32 "
        "{%0,%1,%2,%3}, {%4,%5,%6,%7}, {%8,%9}, {%0,%1,%2,%3};"
        : "+f"(c[0]), "+f"(c[1]), "+f"(c[2]), "+f"(c[3])
        : "r"(a[0]), "r"(a[1]), "r"(a[2]), "r"(a[3]), "r"(b[0]), "r"(b[1]));
}

// Swizzled smem byte offset for (row, 16B-chunk c16) inside a 128x32-fp16 tile.
__device__ __forceinline__ uint32_t sw_off(int row, int c16) {
    return (uint32_t)(row * 64 + ((c16 ^ ((row >> 1) & 3)) << 4));
}

// ---------------------------------------------------------------------------
// fp16 NT GEMM via mma.sync:
//   C[128,128] tile = A[M,K] @ B[N,K]^T, fp32 accumulate.
// Output: fp32 * alpha (outF) or fp16 (outH).
// ---------------------------------------------------------------------------
__global__ __launch_bounds__(256, 1) void gemm_f16(
    const __half* __restrict__ A, const __half* __restrict__ B,
    float* __restrict__ outF, __half* __restrict__ outH,
    int lda, int ldb, int ldc, long sA, long sB, long sC,
    float alpha, int Ktot, int causalSkip, int causalK)
{
    const int m0 = blockIdx.y * BM;
    const int n0 = blockIdx.x * BN;
    if (causalSkip && n0 >= m0 + BM) return;

    extern __shared__ char smem[];
    const uint32_t sb = smem_u32(smem);

    const int tid  = threadIdx.x;
    const int lane = tid & 31;
    const int wid  = tid >> 5;
    const int warpM0 = (wid >> 2) * 64;   // 2 warps along M
    const int warpN0 = (wid & 3) * 32;    // 4 warps along N

    A += (size_t)blockIdx.z * sA;
    B += (size_t)blockIdx.z * sB;

    const int kEnd = causalK ? min(Ktot, m0 + BM) : Ktot;
    const int nCh = kEnd / BK;

    int gr[2], gc[2];
#pragma unroll
    for (int r = 0; r < 2; r++) {
        int i = tid + r * 256;
        gr[r] = i >> 2;        // row 0..127
        gc[r] = i & 3;         // 16B chunk 0..3
    }

    auto issue = [&](int c) {
        const uint32_t st = sb + (uint32_t)(c % STAGES) * STAGE_BYTES;
        const int k0 = c * BK;
#pragma unroll
        for (int r = 0; r < 2; r++) {
            const int row = gr[r], c16 = gc[r];
            const uint32_t so = sw_off(row, c16);
            cp_async16(st + so,             A + (size_t)(m0 + row) * lda + k0 + c16 * 8);
            cp_async16(st + MAT_BYTES + so, B + (size_t)(n0 + row) * ldb + k0 + c16 * 8);
        }
    };

    float acc[4][4][4];
#pragma unroll
    for (int i = 0; i < 4; i++)
#pragma unroll
        for (int j = 0; j < 4; j++)
#pragma unroll
            for (int k = 0; k < 4; k++) acc[i][j][k] = 0.f;

    if (0 < nCh) issue(0);
    CP_COMMIT();
    if (1 < nCh) issue(1);
    CP_COMMIT();

    const int aRow = (lane & 15);
    const int aHi  = (lane >> 4);
    const int bRow = (lane & 7) + ((lane >> 4) << 3);   // B pair: nf / nf+1
    const int bHi  = ((lane >> 3) & 1);

    for (int c = 0; c < nCh; c++) {
        CP_WAIT1();
        __syncthreads();
        if (c + 2 < nCh) issue(c + 2);
        CP_COMMIT();

        const uint32_t st = sb + (uint32_t)(c % STAGES) * STAGE_BYTES;
#pragma unroll
        for (int ks = 0; ks < 2; ks++) {
            uint32_t ah[4][4];
#pragma unroll
            for (int mf = 0; mf < 4; mf++) {
                const int row = warpM0 + mf * 16 + aRow;
                const uint32_t so = sw_off(row, ks * 2 + aHi);
                ldmx4(ah[mf][0], ah[mf][1], ah[mf][2], ah[mf][3], st + so);
            }
#pragma unroll
            for (int nfp = 0; nfp < 2; nfp++) {
                const int row = warpN0 + nfp * 16 + bRow;
                const uint32_t so = sw_off(row, ks * 2 + bHi);
                uint32_t bh[4];
                ldmx4(bh[0], bh[1], bh[2], bh[3], st + MAT_BYTES + so);
#pragma unroll
                for (int mf = 0; mf < 4; mf++) {
                    mma16816(acc[mf][2*nfp],     ah[mf], bh + 0);
                    mma16816(acc[mf][2*nfp + 1], ah[mf], bh + 2);
                }
            }
        }
    }

    // epilogue
    const long cb = (long)blockIdx.z * sC;
    const int rBase = m0 + warpM0 + (lane >> 2);
    const int cBase = n0 + warpN0 + (lane & 3) * 2;
#pragma unroll
    for (int mf = 0; mf < 4; mf++) {
#pragma unroll
        for (int nf = 0; nf < 4; nf++) {
            const int col = cBase + nf * 8;
#pragma unroll
            for (int h = 0; h < 2; h++) {
                const int row = rBase + mf * 16 + h * 8;
                const float v0 = acc[mf][nf][2 * h];
                const float v1 = acc[mf][nf][2 * h + 1];
                if (outF) {
                    *(float2*)(outF + cb + (size_t)row * ldc + col) =
                        make_float2(v0 * alpha, v1 * alpha);
                } else {
                    *(__half2*)(outH + cb + (size_t)row * ldc + col) =
                        __floats2half2_rn(v0, v1);
                }
            }
        }
    }
}

// ---------------------------------------------------------------------------
__global__ __launch_bounds__(256) void to_f16(
    const float* __restrict__ src, __half* __restrict__ dst, int n4)
{
    int i = blockIdx.x * 256 + threadIdx.x;
    if (i >= n4) return;
    float4 v = ((const float4*)src)[i];
    __half2* D = (__half2*)dst + 2 * (size_t)i;
    D[0] = __floats2half2_rn(v.x, v.y);
    D[1] = __floats2half2_rn(v.z, v.w);
}

// src [B][SEQ][DM] -> dst [B][DM][SEQ]
__global__ __launch_bounds__(256) void transpose_f16(
    const __half* __restrict__ src, __half* __restrict__ dst)
{
    __shared__ __half t[64][65];
    const int b  = blockIdx.z;
    const int n0 = blockIdx.x * 64;
    const int k0 = blockIdx.y * 64;
    const int tx = threadIdx.x & 31, ty = threadIdx.x >> 5;

    const __half* s = src + ((size_t)b * SEQ + k0) * DM + n0;
#pragma unroll
    for (int i = 0; i < 8; i++) {
        int r = ty + i * 8;
        __half2 v = *(const __half2*)(s + (size_t)r * DM + 2 * tx);
        t[r][2*tx] = __low2half(v); t[r][2*tx+1] = __high2half(v);
    }
    __syncthreads();
    __half* d = dst + ((size_t)b * DM + n0) * SEQ + k0;
#pragma unroll
    for (int i = 0; i < 8; i++) {
        int rn = ty + i * 8;
        *(__half2*)(d + (size_t)rn * SEQ + 2 * tx) =
            __halves2half2(t[2*tx][rn], t[2*tx+1][rn]);
    }
}

// Causal softmax: fp32 in, fp16 out, zero-fill to the 128-boundary.
__global__ __launch_bounds__(256) void softmax_causal(
    const float* __restrict__ P, __half* __restrict__ P16)
{
    const int q = blockIdx.x, b = blockIdx.y;
    const float* row = P + ((size_t)b * SEQ + q) * SEQ;
    __half* hr = P16 + ((size_t)b * SEQ + q) * SEQ;
    const int len = q + 1, tid = threadIdx.x;

    __shared__ float sred[8];
    __shared__ float sbc;

    float vals[8]; int n = 0;
    float m = -CUDART_INF_F;
    for (int i = tid; i < len; i += 256) { float v = row[i]; vals[n++] = v; m = fmaxf(m, v); }
#pragma unroll
    for (int o = 16; o; o >>= 1) m = fmaxf(m, __shfl_xor_sync(0xffffffffu, m, o));
    if ((tid & 31) == 0) sred[tid >> 5] = m;
    __syncthreads();
    if (tid == 0) {
        float t = sred[0];
#pragma unroll
        for (int w = 1; w < 8; w++) t = fmaxf(t, sred[w]);
        sbc = t;
    }
    __syncthreads();
    m = sbc;

    float s = 0.f;
#pragma unroll
    for (int k = 0; k < 8; k++)
        if (k < n) { float e = expf(vals[k] - m); vals[k] = e; s += e; }
#pragma unroll
    for (int o = 16; o; o >>= 1) s += __shfl_xor_sync(0xffffffffu, s, o);
    __syncthreads();
    if ((tid & 31) == 0) sred[tid >> 5] = s;
    __syncthreads();
    if (tid == 0) {
        float t = 0.f;
#pragma unroll
        for (int w = 0; w < 8; w++) t += sred[w];
        sbc = 1.f / t;
    }
    __syncthreads();
    const float inv = sbc;

    n = 0;
    for (int i = tid; i < len; i += 256) hr[i] = __float2half_rn(vals[n++] * inv);

    const __half z = __float2half_rn(0.f);
    const int tileEnd = ((q >> 7) + 1) << 7;
    for (int i = len + tid; i < tileEnd; i += 256) hr[i] = z;
}

// ---------------------------------------------------------------------------
extern "C" void kernel_launch(void* const* d_in, const int* in_sizes, int n_in,
                              void* d_out, int out_size)
{
    const float* x  = (const float*)d_in[0];
    const float* Wq = (const float*)d_in[1];
    const float* Wk = (const float*)d_in[2];
    const float* Wv = (const float*)d_in[3];
    float* out = (float*)d_out;

    __half *x16, *W16, *QKV16, *Vt16, *P16;
    float *Pf;
    cudaGetSymbolAddress((void**)&x16, g_x16);
    cudaGetSymbolAddress((void**)&W16, g_W16);
    cudaGetSymbolAddress((void**)&QKV16, g_QKV16);
    cudaGetSymbolAddress((void**)&Vt16, g_Vt16);
    cudaGetSymbolAddress((void**)&Pf, g_Pf);
    cudaGetSymbolAddress((void**)&P16, g_P16);

    const long BSD = (long)BATCH * SEQ * DM;
    const long SD  = (long)SEQ * DM;
    const long SS  = (long)SEQ * SEQ;

    cudaFuncSetAttribute(gemm_f16, cudaFuncAttributeMaxDynamicSharedMemorySize, SMEM_TOTAL);

    // 1) fp32 -> fp16 conversions
    to_f16<<<(BATCH*SEQ*DM/4 + 255)/256, 256>>>(x, x16, BATCH*SEQ*DM/4);
    to_f16<<<(DM*DM/4 + 255)/256, 256>>>(Wq, W16,               DM*DM/4);
    to_f16<<<(DM*DM/4 + 255)/256, 256>>>(Wk, W16 + (long)DM*DM, DM*DM/4);
    to_f16<<<(DM*DM/4 + 255)/256, 256>>>(Wv, W16 + 2L*DM*DM,    DM*DM/4);

    // 2) Fused QKV projection (z selects weight + output section; A fixed)
    {
        dim3 g(DM / BN, (BATCH * SEQ) / BM, 3);
        gemm_f16<<<g, 256, SMEM_TOTAL>>>(x16, W16,
            nullptr, QKV16,
            DM, DM, DM, 0, (long)DM * DM, BSD,
            1.f, DM, 0, 0);
    }

    // 3) V transpose: [B][S][DM] -> [B][DM][S]
    {
        dim3 g(DM / 64, SEQ / 64, BATCH);
        transpose_f16<<<g, 256>>>(QKV16 + 2 * BSD, Vt16);
    }

    // 4) Scores: P = (1/32) Q @ K^T (causal tile skip)
    {
        dim3 g(SEQ / BN, SEQ / BM, BATCH);
        gemm_f16<<<g, 256, SMEM_TOTAL>>>(QKV16, QKV16 + BSD,
            Pf, nullptr,
            DM, DM, SEQ, SD, SD, SS,
            0.03125f, DM, 1, 0);
    }

    // 5) Causal softmax -> fp16 P (+ zero fill to 128-boundary)
    softmax_causal<<<dim3(SEQ, BATCH), 256>>>(Pf, P16);

    // 6) O = P @ V   (B operand = V^T, K-major over S; K truncated at diag)
    {
        dim3 g(DM / BN, SEQ / BM, BATCH);
        gemm_f16<<<g, 256, SMEM_TOTAL>>>(P16, Vt16,
            out, nullptr,
            SEQ, SEQ, DM, SS, SD, SD,
            1.f, SEQ, 0, 1);
    }
}

// round 8
// speedup vs baseline: 5.9115x; 1.0559x over previous
#include <cuda_runtime.h>
#include <cuda_fp16.h>
#include <math_constants.h>
#include <cstdint>

#define BATCH 4
#define SEQ   2048
#define DM    1024

#define BM 128
#define BN 256
#define BK 32                      // fp16 per chunk (64 bytes per row)
#define STAGES 3
#define A_BYTES (128 * 64)         // 128x32 fp16 = 8192 B
#define B_BYTES (256 * 64)         // 256x32 fp16 = 16384 B
#define STAGE_BYTES (A_BYTES + B_BYTES)    // 24576 B
#define SMEM_TOTAL (STAGES * STAGE_BYTES)  // 73728 B

// ---------------------------------------------------------------------------
// Scratch (allocation-free)
// ---------------------------------------------------------------------------
__device__ __half g_x16[(size_t)BATCH*SEQ*DM];
__device__ __half g_W16[(size_t)3*DM*DM];
__device__ __half g_QKV16[(size_t)3*BATCH*SEQ*DM];
__device__ __half g_Vt16[(size_t)BATCH*DM*SEQ];
__device__ __half g_P16[(size_t)BATCH*SEQ*SEQ];

// ---------------------------------------------------------------------------
// PTX helpers (base sm_80+ features only)
// ---------------------------------------------------------------------------
__device__ __forceinline__ uint32_t smem_u32(const void* p) {
    uint32_t a;
    asm("{ .reg .u64 t; cvta.to.shared.u64 t, %1; cvt.u32.u64 %0, t; }" : "=r"(a) : "l"(p));
    return a;
}
__device__ __forceinline__ void cp_async16(uint32_t s, const void* g) {
    asm volatile("cp.async.cg.shared.global [%0], [%1], 16;" :: "r"(s), "l"(g));
}
#define CP_COMMIT() asm volatile("cp.async.commit_group;" ::: "memory")
#define CP_WAIT1()  asm volatile("cp.async.wait_group 1;" ::: "memory")

__device__ __forceinline__ void ldmx4(uint32_t& r0, uint32_t& r1, uint32_t& r2, uint32_t& r3,
                                      uint32_t a) {
    asm volatile("ldmatrix.sync.aligned.m8n8.x4.shared.b16 {%0,%1,%2,%3}, [%4];"
        : "=r"(r0), "=r"(r1), "=r"(r2), "=r"(r3) : "r"(a));
}
__device__ __forceinline__ void mma16816(float* c, const uint32_t* a, const uint32_t* b) {
    asm volatile("mma.sync.aligned.m16n8k16.row.col.f32.f16.f16.f32 "
        "{%0,%1,%2,%3}, {%4,%5,%6,%7}, {%8,%9}, {%0,%1,%2,%3};"
        : "+f"(c[0]), "+f"(c[1]), "+f"(c[2]), "+f"(c[3])
        : "r"(a[0]), "r"(a[1]), "r"(a[2]), "r"(a[3]), "r"(b[0]), "r"(b[1]));
}

// Swizzled smem byte offset for (row, 16B-chunk c16) inside an Nx32-fp16 tile.
__device__ __forceinline__ uint32_t sw_off(int row, int c16) {
    return (uint32_t)(row * 64 + ((c16 ^ ((row >> 1) & 3)) << 4));
}

// ---------------------------------------------------------------------------
// fp16 NT GEMM via mma.sync: C[128,256] = A[M,K] @ B[N,K]^T, fp32 accumulate.
// Warp tile 64x64 (8 warps: 2 along M x 4 along N).
// ---------------------------------------------------------------------------
__global__ __launch_bounds__(256, 1) void gemm_f16(
    const __half* __restrict__ A, const __half* __restrict__ B,
    float* __restrict__ outF, __half* __restrict__ outH,
    int lda, int ldb, int ldc, long sA, long sB, long sC,
    float alpha, int Ktot, int causalSkip, int causalK)
{
    const int m0 = blockIdx.y * BM;
    const int n0 = blockIdx.x * BN;
    if (causalSkip && n0 >= m0 + BM) return;

    extern __shared__ char smem[];
    const uint32_t sb = smem_u32(smem);

    const int tid  = threadIdx.x;
    const int lane = tid & 31;
    const int wid  = tid >> 5;
    const int warpM0 = (wid >> 2) * 64;   // 2 warps along M
    const int warpN0 = (wid & 3) * 64;    // 4 warps along N

    A += (size_t)blockIdx.z * sA;
    B += (size_t)blockIdx.z * sB;

    const int kEnd = causalK ? min(Ktot, m0 + BM) : Ktot;
    const int nCh = kEnd / BK;

    auto issue = [&](int c) {
        const uint32_t st = sb + (uint32_t)(c % STAGES) * STAGE_BYTES;
        const int k0 = c * BK;
        // A: 512 16B chunks (2 per thread)
#pragma unroll
        for (int r = 0; r < 2; r++) {
            const int i = tid + r * 256;
            const int row = i >> 2, c16 = i & 3;
            cp_async16(st + sw_off(row, c16),
                       A + (size_t)(m0 + row) * lda + k0 + c16 * 8);
        }
        // B: 1024 16B chunks (4 per thread)
#pragma unroll
        for (int r = 0; r < 4; r++) {
            const int i = tid + r * 256;
            const int row = i >> 2, c16 = i & 3;
            cp_async16(st + A_BYTES + sw_off(row, c16),
                       B + (size_t)(n0 + row) * ldb + k0 + c16 * 8);
        }
    };

    float acc[4][8][4];
#pragma unroll
    for (int i = 0; i < 4; i++)
#pragma unroll
        for (int j = 0; j < 8; j++)
#pragma unroll
            for (int k = 0; k < 4; k++) acc[i][j][k] = 0.f;

    if (0 < nCh) issue(0);
    CP_COMMIT();
    if (1 < nCh) issue(1);
    CP_COMMIT();

    const int aRow = (lane & 15);
    const int aHi  = (lane >> 4);
    const int bRow = (lane & 7) + ((lane >> 4) << 3);   // B pair: nf / nf+1
    const int bHi  = ((lane >> 3) & 1);

    for (int c = 0; c < nCh; c++) {
        CP_WAIT1();
        __syncthreads();
        if (c + 2 < nCh) issue(c + 2);
        CP_COMMIT();

        const uint32_t st = sb + (uint32_t)(c % STAGES) * STAGE_BYTES;
#pragma unroll
        for (int ks = 0; ks < 2; ks++) {
            uint32_t ah[4][4];
#pragma unroll
            for (int mf = 0; mf < 4; mf++) {
                const int row = warpM0 + mf * 16 + aRow;
                ldmx4(ah[mf][0], ah[mf][1], ah[mf][2], ah[mf][3],
                      st + sw_off(row, ks * 2 + aHi));
            }
#pragma unroll
            for (int nfp = 0; nfp < 4; nfp++) {
                const int row = warpN0 + nfp * 16 + bRow;
                uint32_t bh[4];
                ldmx4(bh[0], bh[1], bh[2], bh[3],
                      st + A_BYTES + sw_off(row, ks * 2 + bHi));
#pragma unroll
                for (int mf = 0; mf < 4; mf++) {
                    mma16816(acc[mf][2*nfp],     ah[mf], bh + 0);
                    mma16816(acc[mf][2*nfp + 1], ah[mf], bh + 2);
                }
            }
        }
    }

    // epilogue
    const long cb = (long)blockIdx.z * sC;
    const int rBase = m0 + warpM0 + (lane >> 2);
    const int cBase = n0 + warpN0 + (lane & 3) * 2;
#pragma unroll
    for (int mf = 0; mf < 4; mf++) {
#pragma unroll
        for (int nf = 0; nf < 8; nf++) {
            const int col = cBase + nf * 8;
#pragma unroll
            for (int h = 0; h < 2; h++) {
                const int row = rBase + mf * 16 + h * 8;
                const float v0 = acc[mf][nf][2 * h] * alpha;
                const float v1 = acc[mf][nf][2 * h + 1] * alpha;
                if (outF) {
                    *(float2*)(outF + cb + (size_t)row * ldc + col) =
                        make_float2(v0, v1);
                } else {
                    *(__half2*)(outH + cb + (size_t)row * ldc + col) =
                        __floats2half2_rn(v0, v1);
                }
            }
        }
    }
}

// ---------------------------------------------------------------------------
__global__ __launch_bounds__(256) void to_f16(
    const float* __restrict__ src, __half* __restrict__ dst, int n4)
{
    int i = blockIdx.x * 256 + threadIdx.x;
    if (i >= n4) return;
    float4 v = ((const float4*)src)[i];
    __half2* D = (__half2*)dst + 2 * (size_t)i;
    D[0] = __floats2half2_rn(v.x, v.y);
    D[1] = __floats2half2_rn(v.z, v.w);
}

// src [B][SEQ][DM] -> dst [B][DM][SEQ]
__global__ __launch_bounds__(256) void transpose_f16(
    const __half* __restrict__ src, __half* __restrict__ dst)
{
    __shared__ __half t[64][65];
    const int b  = blockIdx.z;
    const int n0 = blockIdx.x * 64;
    const int k0 = blockIdx.y * 64;
    const int tx = threadIdx.x & 31, ty = threadIdx.x >> 5;

    const __half* s = src + ((size_t)b * SEQ + k0) * DM + n0;
#pragma unroll
    for (int i = 0; i < 8; i++) {
        int r = ty + i * 8;
        __half2 v = *(const __half2*)(s + (size_t)r * DM + 2 * tx);
        t[r][2*tx] = __low2half(v); t[r][2*tx+1] = __high2half(v);
    }
    __syncthreads();
    __half* d = dst + ((size_t)b * DM + n0) * SEQ + k0;
#pragma unroll
    for (int i = 0; i < 8; i++) {
        int rn = ty + i * 8;
        *(__half2*)(d + (size_t)rn * SEQ + 2 * tx) =
            __halves2half2(t[2*tx][rn], t[2*tx+1][rn]);
    }
}

// Causal softmax, in place on fp16 P. Reads k <= q only; zero-fills (q, 128-boundary).
__global__ __launch_bounds__(256) void softmax_causal(__half* __restrict__ P16)
{
    const int q = blockIdx.x, b = blockIdx.y;
    __half* row = P16 + ((size_t)b * SEQ + q) * SEQ;
    const int len = q + 1, tid = threadIdx.x;

    __shared__ float sred[8];
    __shared__ float sbc;

    float vals[8]; int n = 0;
    float m = -CUDART_INF_F;
    for (int i = tid; i < len; i += 256) {
        float v = __half2float(row[i]);
        vals[n++] = v;
        m = fmaxf(m, v);
    }
#pragma unroll
    for (int o = 16; o; o >>= 1) m = fmaxf(m, __shfl_xor_sync(0xffffffffu, m, o));
    if ((tid & 31) == 0) sred[tid >> 5] = m;
    __syncthreads();
    if (tid == 0) {
        float t = sred[0];
#pragma unroll
        for (int w = 1; w < 8; w++) t = fmaxf(t, sred[w]);
        sbc = t;
    }
    __syncthreads();
    m = sbc;

    float s = 0.f;
#pragma unroll
    for (int k = 0; k < 8; k++)
        if (k < n) { float e = expf(vals[k] - m); vals[k] = e; s += e; }
#pragma unroll
    for (int o = 16; o; o >>= 1) s += __shfl_xor_sync(0xffffffffu, s, o);
    __syncthreads();
    if ((tid & 31) == 0) sred[tid >> 5] = s;
    __syncthreads();
    if (tid == 0) {
        float t = 0.f;
#pragma unroll
        for (int w = 0; w < 8; w++) t += sred[w];
        sbc = 1.f / t;
    }
    __syncthreads();
    const float inv = sbc;

    n = 0;
    for (int i = tid; i < len; i += 256) row[i] = __float2half_rn(vals[n++] * inv);

    const __half z = __float2half_rn(0.f);
    const int tileEnd = ((q >> 7) + 1) << 7;
    for (int i = len + tid; i < tileEnd; i += 256) row[i] = z;
}

// ---------------------------------------------------------------------------
extern "C" void kernel_launch(void* const* d_in, const int* in_sizes, int n_in,
                              void* d_out, int out_size)
{
    const float* x  = (const float*)d_in[0];
    const float* Wq = (const float*)d_in[1];
    const float* Wk = (const float*)d_in[2];
    const float* Wv = (const float*)d_in[3];
    float* out = (float*)d_out;

    __half *x16, *W16, *QKV16, *Vt16, *P16;
    cudaGetSymbolAddress((void**)&x16, g_x16);
    cudaGetSymbolAddress((void**)&W16, g_W16);
    cudaGetSymbolAddress((void**)&QKV16, g_QKV16);
    cudaGetSymbolAddress((void**)&Vt16, g_Vt16);
    cudaGetSymbolAddress((void**)&P16, g_P16);

    const long BSD = (long)BATCH * SEQ * DM;
    const long SD  = (long)SEQ * DM;
    const long SS  = (long)SEQ * SEQ;

    cudaFuncSetAttribute(gemm_f16, cudaFuncAttributeMaxDynamicSharedMemorySize, SMEM_TOTAL);

    // 1) fp32 -> fp16 conversions
    to_f16<<<(BATCH*SEQ*DM/4 + 255)/256, 256>>>(x, x16, BATCH*SEQ*DM/4);
    to_f16<<<(DM*DM/4 + 255)/256, 256>>>(Wq, W16,               DM*DM/4);
    to_f16<<<(DM*DM/4 + 255)/256, 256>>>(Wk, W16 + (long)DM*DM, DM*DM/4);
    to_f16<<<(DM*DM/4 + 255)/256, 256>>>(Wv, W16 + 2L*DM*DM,    DM*DM/4);

    // 2) Fused QKV projection (z selects weight + output section; A fixed)
    {
        dim3 g(DM / BN, (BATCH * SEQ) / BM, 3);
        gemm_f16<<<g, 256, SMEM_TOTAL>>>(x16, W16,
            nullptr, QKV16,
            DM, DM, DM, 0, (long)DM * DM, BSD,
            1.f, DM, 0, 0);
    }

    // 3) V transpose: [B][S][DM] -> [B][DM][S]
    {
        dim3 g(DM / 64, SEQ / 64, BATCH);
        transpose_f16<<<g, 256>>>(QKV16 + 2 * BSD, Vt16);
    }

    // 4) Scores -> fp16 P directly: P = (1/32) Q @ K^T (causal tile skip)
    {
        dim3 g(SEQ / BN, SEQ / BM, BATCH);
        gemm_f16<<<g, 256, SMEM_TOTAL>>>(QKV16, QKV16 + BSD,
            nullptr, P16,
            DM, DM, SEQ, SD, SD, SS,
            0.03125f, DM, 1, 0);
    }

    // 5) Causal softmax in place on fp16 P (+ zero fill to 128-boundary)
    softmax_causal<<<dim3(SEQ, BATCH), 256>>>(P16);

    // 6) O = P @ V   (B operand = V^T, K-major over S; K truncated at diag)
    {
        dim3 g(DM / BN, SEQ / BM, BATCH);
        gemm_f16<<<g, 256, SMEM_TOTAL>>>(P16, Vt16,
            out, nullptr,
            SEQ, SEQ, DM, SS, SD, SD,
            1.f, SEQ, 0, 1);
    }
}

// round 9
// speedup vs baseline: 6.1424x; 1.0391x over previous
#include <cuda_runtime.h>
#include <cuda_fp16.h>
#include <math_constants.h>
#include <cstdint>

#define BATCH 4
#define SEQ   2048
#define DM    1024

#define BM 128
#define BN 256
#define BK 32                      // fp16 per chunk (64 bytes per row)
#define STAGES 3
#define A_BYTES (128 * 64)         // 128x32 fp16 = 8192 B
#define B_BYTES (256 * 64)         // 256x32 fp16 = 16384 B
#define STAGE_BYTES (A_BYTES + B_BYTES)    // 24576 B
#define SMEM_TOTAL (STAGES * STAGE_BYTES)  // 73728 B

// ---------------------------------------------------------------------------
// Scratch (allocation-free)
// ---------------------------------------------------------------------------
__device__ __half g_x16[(size_t)BATCH*SEQ*DM];
__device__ __half g_W16[(size_t)3*DM*DM];
__device__ __half g_QKV16[(size_t)3*BATCH*SEQ*DM];
__device__ __half g_Vt16[(size_t)BATCH*DM*SEQ];
__device__ __half g_P16[(size_t)BATCH*SEQ*SEQ];

// ---------------------------------------------------------------------------
// PTX helpers (base sm_80+ features only)
// ---------------------------------------------------------------------------
__device__ __forceinline__ uint32_t smem_u32(const void* p) {
    uint32_t a;
    asm("{ .reg .u64 t; cvta.to.shared.u64 t, %1; cvt.u32.u64 %0, t; }" : "=r"(a) : "l"(p));
    return a;
}
__device__ __forceinline__ void cp_async16(uint32_t s, const void* g) {
    asm volatile("cp.async.cg.shared.global [%0], [%1], 16;" :: "r"(s), "l"(g));
}
#define CP_COMMIT() asm volatile("cp.async.commit_group;" ::: "memory")
#define CP_WAIT1()  asm volatile("cp.async.wait_group 1;" ::: "memory")

__device__ __forceinline__ void ldmx4(uint32_t& r0, uint32_t& r1, uint32_t& r2, uint32_t& r3,
                                      uint32_t a) {
    asm volatile("ldmatrix.sync.aligned.m8n8.x4.shared.b16 {%0,%1,%2,%3}, [%4];"
        : "=r"(r0), "=r"(r1), "=r"(r2), "=r"(r3) : "r"(a));
}
__device__ __forceinline__ void mma16816(float* c, const uint32_t* a, const uint32_t* b) {
    asm volatile("mma.sync.aligned.m16n8k16.row.col.f32.f16.f16.f32 "
        "{%0,%1,%2,%3}, {%4,%5,%6,%7}, {%8,%9}, {%0,%1,%2,%3};"
        : "+f"(c[0]), "+f"(c[1]), "+f"(c[2]), "+f"(c[3])
        : "r"(a[0]), "r"(a[1]), "r"(a[2]), "r"(a[3]), "r"(b[0]), "r"(b[1]));
}

// Swizzled smem byte offset for (row, 16B-chunk c16) inside an Nx32-fp16 tile.
__device__ __forceinline__ uint32_t sw_off(int row, int c16) {
    return (uint32_t)(row * 64 + ((c16 ^ ((row >> 1) & 3)) << 4));
}

// ---------------------------------------------------------------------------
// fp16 NT GEMM via mma.sync: C[128,256] = A[M,K] @ B[N,K]^T, fp32 accumulate.
// Warp tile 64x64 (8 warps: 2 along M x 4 along N).
// revM: process m-tiles in reverse bid order (LPT schedule for causal-K).
// ---------------------------------------------------------------------------
__global__ __launch_bounds__(256, 1) void gemm_f16(
    const __half* __restrict__ A, const __half* __restrict__ B,
    float* __restrict__ outF, __half* __restrict__ outH,
    int lda, int ldb, int ldc, long sA, long sB, long sC,
    float alpha, int Ktot, int causalSkip, int causalK, int revM)
{
    const int mTile = revM ? (int)(gridDim.y - 1 - blockIdx.y) : (int)blockIdx.y;
    const int m0 = mTile * BM;
    const int n0 = blockIdx.x * BN;
    if (causalSkip && n0 >= m0 + BM) return;

    extern __shared__ char smem[];
    const uint32_t sb = smem_u32(smem);

    const int tid  = threadIdx.x;
    const int lane = tid & 31;
    const int wid  = tid >> 5;
    const int warpM0 = (wid >> 2) * 64;   // 2 warps along M
    const int warpN0 = (wid & 3) * 64;    // 4 warps along N

    A += (size_t)blockIdx.z * sA;
    B += (size_t)blockIdx.z * sB;

    const int kEnd = causalK ? min(Ktot, m0 + BM) : Ktot;
    const int nCh = kEnd / BK;

    auto issue = [&](int c) {
        const uint32_t st = sb + (uint32_t)(c % STAGES) * STAGE_BYTES;
        const int k0 = c * BK;
#pragma unroll
        for (int r = 0; r < 2; r++) {
            const int i = tid + r * 256;
            const int row = i >> 2, c16 = i & 3;
            cp_async16(st + sw_off(row, c16),
                       A + (size_t)(m0 + row) * lda + k0 + c16 * 8);
        }
#pragma unroll
        for (int r = 0; r < 4; r++) {
            const int i = tid + r * 256;
            const int row = i >> 2, c16 = i & 3;
            cp_async16(st + A_BYTES + sw_off(row, c16),
                       B + (size_t)(n0 + row) * ldb + k0 + c16 * 8);
        }
    };

    float acc[4][8][4];
#pragma unroll
    for (int i = 0; i < 4; i++)
#pragma unroll
        for (int j = 0; j < 8; j++)
#pragma unroll
            for (int k = 0; k < 4; k++) acc[i][j][k] = 0.f;

    if (0 < nCh) issue(0);
    CP_COMMIT();
    if (1 < nCh) issue(1);
    CP_COMMIT();

    const int aRow = (lane & 15);
    const int aHi  = (lane >> 4);
    const int bRow = (lane & 7) + ((lane >> 4) << 3);
    const int bHi  = ((lane >> 3) & 1);

    for (int c = 0; c < nCh; c++) {
        CP_WAIT1();
        __syncthreads();
        if (c + 2 < nCh) issue(c + 2);
        CP_COMMIT();

        const uint32_t st = sb + (uint32_t)(c % STAGES) * STAGE_BYTES;
#pragma unroll
        for (int ks = 0; ks < 2; ks++) {
            uint32_t ah[4][4];
#pragma unroll
            for (int mf = 0; mf < 4; mf++) {
                const int row = warpM0 + mf * 16 + aRow;
                ldmx4(ah[mf][0], ah[mf][1], ah[mf][2], ah[mf][3],
                      st + sw_off(row, ks * 2 + aHi));
            }
#pragma unroll
            for (int nfp = 0; nfp < 4; nfp++) {
                const int row = warpN0 + nfp * 16 + bRow;
                uint32_t bh[4];
                ldmx4(bh[0], bh[1], bh[2], bh[3],
                      st + A_BYTES + sw_off(row, ks * 2 + bHi));
#pragma unroll
                for (int mf = 0; mf < 4; mf++) {
                    mma16816(acc[mf][2*nfp],     ah[mf], bh + 0);
                    mma16816(acc[mf][2*nfp + 1], ah[mf], bh + 2);
                }
            }
        }
    }

    // epilogue
    const long cb = (long)blockIdx.z * sC;
    const int rBase = m0 + warpM0 + (lane >> 2);
    const int cBase = n0 + warpN0 + (lane & 3) * 2;
#pragma unroll
    for (int mf = 0; mf < 4; mf++) {
#pragma unroll
        for (int nf = 0; nf < 8; nf++) {
            const int col = cBase + nf * 8;
#pragma unroll
            for (int h = 0; h < 2; h++) {
                const int row = rBase + mf * 16 + h * 8;
                const float v0 = acc[mf][nf][2 * h] * alpha;
                const float v1 = acc[mf][nf][2 * h + 1] * alpha;
                if (outF) {
                    *(float2*)(outF + cb + (size_t)row * ldc + col) =
                        make_float2(v0, v1);
                } else {
                    *(__half2*)(outH + cb + (size_t)row * ldc + col) =
                        __floats2half2_rn(v0, v1);
                }
            }
        }
    }
}

// ---------------------------------------------------------------------------
// One fused fp32->fp16 convert for x, Wq, Wk, Wv.
// ---------------------------------------------------------------------------
#define XN4 (BATCH*SEQ*DM/4)
#define WN4 (DM*DM/4)
__global__ __launch_bounds__(256) void to_f16_all(
    const float* __restrict__ x, const float* __restrict__ Wq,
    const float* __restrict__ Wk, const float* __restrict__ Wv,
    __half* __restrict__ x16, __half* __restrict__ W16)
{
    int i = blockIdx.x * 256 + threadIdx.x;
    const float* src;
    __half* dst;
    int off;
    if (i < XN4) { src = x; dst = x16; off = i; }
    else {
        int j = i - XN4;
        int w = j / WN4;
        off = j - w * WN4;
        src = (w == 0) ? Wq : (w == 1) ? Wk : Wv;
        dst = W16 + (size_t)w * DM * DM / 4 * 4;
        if (i >= XN4 + 3 * WN4) return;
    }
    float4 v = ((const float4*)src)[off];
    __half2* D = (__half2*)dst + 2 * (size_t)off;
    D[0] = __floats2half2_rn(v.x, v.y);
    D[1] = __floats2half2_rn(v.z, v.w);
}

// src [B][SEQ][DM] -> dst [B][DM][SEQ]
__global__ __launch_bounds__(256) void transpose_f16(
    const __half* __restrict__ src, __half* __restrict__ dst)
{
    __shared__ __half t[64][65];
    const int b  = blockIdx.z;
    const int n0 = blockIdx.x * 64;
    const int k0 = blockIdx.y * 64;
    const int tx = threadIdx.x & 31, ty = threadIdx.x >> 5;

    const __half* s = src + ((size_t)b * SEQ + k0) * DM + n0;
#pragma unroll
    for (int i = 0; i < 8; i++) {
        int r = ty + i * 8;
        __half2 v = *(const __half2*)(s + (size_t)r * DM + 2 * tx);
        t[r][2*tx] = __low2half(v); t[r][2*tx+1] = __high2half(v);
    }
    __syncthreads();
    __half* d = dst + ((size_t)b * DM + n0) * SEQ + k0;
#pragma unroll
    for (int i = 0; i < 8; i++) {
        int rn = ty + i * 8;
        *(__half2*)(d + (size_t)rn * SEQ + 2 * tx) =
            __halves2half2(t[2*tx][rn], t[2*tx+1][rn]);
    }
}

// Causal softmax, in place on fp16 P. Reads k <= q only; zero-fills (q, 128-boundary).
__global__ __launch_bounds__(256) void softmax_causal(__half* __restrict__ P16)
{
    const int q = blockIdx.x, b = blockIdx.y;
    __half* row = P16 + ((size_t)b * SEQ + q) * SEQ;
    const int len = q + 1, tid = threadIdx.x;

    __shared__ float sred[8];
    __shared__ float sbc;

    float vals[8]; int n = 0;
    float m = -CUDART_INF_F;
    for (int i = tid; i < len; i += 256) {
        float v = __half2float(row[i]);
        vals[n++] = v;
        m = fmaxf(m, v);
    }
#pragma unroll
    for (int o = 16; o; o >>= 1) m = fmaxf(m, __shfl_xor_sync(0xffffffffu, m, o));
    if ((tid & 31) == 0) sred[tid >> 5] = m;
    __syncthreads();
    if (tid == 0) {
        float t = sred[0];
#pragma unroll
        for (int w = 1; w < 8; w++) t = fmaxf(t, sred[w]);
        sbc = t;
    }
    __syncthreads();
    m = sbc;

    float s = 0.f;
#pragma unroll
    for (int k = 0; k < 8; k++)
        if (k < n) { float e = expf(vals[k] - m); vals[k] = e; s += e; }
#pragma unroll
    for (int o = 16; o; o >>= 1) s += __shfl_xor_sync(0xffffffffu, s, o);
    __syncthreads();
    if ((tid & 31) == 0) sred[tid >> 5] = s;
    __syncthreads();
    if (tid == 0) {
        float t = 0.f;
#pragma unroll
        for (int w = 0; w < 8; w++) t += sred[w];
        sbc = 1.f / t;
    }
    __syncthreads();
    const float inv = sbc;

    n = 0;
    for (int i = tid; i < len; i += 256) row[i] = __float2half_rn(vals[n++] * inv);

    const __half z = __float2half_rn(0.f);
    const int tileEnd = ((q >> 7) + 1) << 7;
    for (int i = len + tid; i < tileEnd; i += 256) row[i] = z;
}

// ---------------------------------------------------------------------------
extern "C" void kernel_launch(void* const* d_in, const int* in_sizes, int n_in,
                              void* d_out, int out_size)
{
    const float* x  = (const float*)d_in[0];
    const float* Wq = (const float*)d_in[1];
    const float* Wk = (const float*)d_in[2];
    const float* Wv = (const float*)d_in[3];
    float* out = (float*)d_out;

    __half *x16, *W16, *QKV16, *Vt16, *P16;
    cudaGetSymbolAddress((void**)&x16, g_x16);
    cudaGetSymbolAddress((void**)&W16, g_W16);
    cudaGetSymbolAddress((void**)&QKV16, g_QKV16);
    cudaGetSymbolAddress((void**)&Vt16, g_Vt16);
    cudaGetSymbolAddress((void**)&P16, g_P16);

    const long BSD = (long)BATCH * SEQ * DM;
    const long SD  = (long)SEQ * DM;
    const long SS  = (long)SEQ * SEQ;

    cudaFuncSetAttribute(gemm_f16, cudaFuncAttributeMaxDynamicSharedMemorySize, SMEM_TOTAL);

    // 1) fused fp32 -> fp16 conversion (x + Wq + Wk + Wv)
    {
        const int total = XN4 + 3 * WN4;
        to_f16_all<<<(total + 255) / 256, 256>>>(x, Wq, Wk, Wv, x16, W16);
    }

    // 2) Fused QKV projection (z selects weight + output section; A fixed)
    {
        dim3 g(DM / BN, (BATCH * SEQ) / BM, 3);
        gemm_f16<<<g, 256, SMEM_TOTAL>>>(x16, W16,
            nullptr, QKV16,
            DM, DM, DM, 0, (long)DM * DM, BSD,
            1.f, DM, 0, 0, 0);
    }

    // 3) V transpose: [B][S][DM] -> [B][DM][S]
    {
        dim3 g(DM / 64, SEQ / 64, BATCH);
        transpose_f16<<<g, 256>>>(QKV16 + 2 * BSD, Vt16);
    }

    // 4) Scores -> fp16 P directly: P = (1/32) Q @ K^T (causal tile skip)
    {
        dim3 g(SEQ / BN, SEQ / BM, BATCH);
        gemm_f16<<<g, 256, SMEM_TOTAL>>>(QKV16, QKV16 + BSD,
            nullptr, P16,
            DM, DM, SEQ, SD, SD, SS,
            0.03125f, DM, 1, 0, 0);
    }

    // 5) Causal softmax in place on fp16 P (+ zero fill to 128-boundary)
    softmax_causal<<<dim3(SEQ, BATCH), 256>>>(P16);

    // 6) O = P @ V (K truncated at diagonal; longest m-tiles issued FIRST)
    {
        dim3 g(DM / BN, SEQ / BM, BATCH);
        gemm_f16<<<g, 256, SMEM_TOTAL>>>(P16, Vt16,
            out, nullptr,
            SEQ, SEQ, DM, SS, SD, SD,
            1.f, SEQ, 0, 1, 1);
    }
}

// round 10
// speedup vs baseline: 7.0733x; 1.1516x over previous
#include <cuda_runtime.h>
#include <cuda_fp16.h>
#include <math_constants.h>
#include <cstdint>

#define BATCH 4
#define SEQ   2048
#define DM    1024

#define BM 128
#define BN 128
#define BK 32                      // fp16 per chunk (64 bytes per row)
#define STAGES 4
#define MAT_BYTES (128 * 64)       // 128x32 fp16 = 8192 B
#define STAGE_BYTES (2 * MAT_BYTES)        // A + B = 16384 B
#define SMEM_TOTAL (STAGES * STAGE_BYTES)  // 65536 B (x2 CTAs = 128 KB/SM)

// ---------------------------------------------------------------------------
// Scratch (allocation-free)
// ---------------------------------------------------------------------------
__device__ __half g_x16[(size_t)BATCH*SEQ*DM];
__device__ __half g_W16[(size_t)3*DM*DM];
__device__ __half g_QKV16[(size_t)3*BATCH*SEQ*DM];
__device__ __half g_Vt16[(size_t)BATCH*DM*SEQ];
__device__ __half g_P16[(size_t)BATCH*SEQ*SEQ];

// ---------------------------------------------------------------------------
// PTX helpers (base sm_80+ features only)
// ---------------------------------------------------------------------------
__device__ __forceinline__ uint32_t smem_u32(const void* p) {
    uint32_t a;
    asm("{ .reg .u64 t; cvta.to.shared.u64 t, %1; cvt.u32.u64 %0, t; }" : "=r"(a) : "l"(p));
    return a;
}
__device__ __forceinline__ void cp_async16(uint32_t s, const void* g) {
    asm volatile("cp.async.cg.shared.global [%0], [%1], 16;" :: "r"(s), "l"(g));
}
#define CP_COMMIT() asm volatile("cp.async.commit_group;" ::: "memory")
#define CP_WAIT2()  asm volatile("cp.async.wait_group 2;" ::: "memory")

__device__ __forceinline__ void ldmx4(uint32_t& r0, uint32_t& r1, uint32_t& r2, uint32_t& r3,
                                      uint32_t a) {
    asm volatile("ldmatrix.sync.aligned.m8n8.x4.shared.b16 {%0,%1,%2,%3}, [%4];"
        : "=r"(r0), "=r"(r1), "=r"(r2), "=r"(r3) : "r"(a));
}
__device__ __forceinline__ void mma16816(float* c, const uint32_t* a, const uint32_t* b) {
    asm volatile("mma.sync.aligned.m16n8k16.row.col.f32.f16.f16.f32 "
        "{%0,%1,%2,%3}, {%4,%5,%6,%7}, {%8,%9}, {%0,%1,%2,%3};"
        : "+f"(c[0]), "+f"(c[1]), "+f"(c[2]), "+f"(c[3])
        : "r"(a[0]), "r"(a[1]), "r"(a[2]), "r"(a[3]), "r"(b[0]), "r"(b[1]));
}

// Swizzled smem byte offset for (row, 16B-chunk c16) inside a 128x32-fp16 tile.
__device__ __forceinline__ uint32_t sw_off(int row, int c16) {
    return (uint32_t)(row * 64 + ((c16 ^ ((row >> 1) & 3)) << 4));
}

// ---------------------------------------------------------------------------
// fp16 NT GEMM via mma.sync: C[128,128] = A[M,K] @ B[N,K]^T, fp32 accumulate.
// Warp tile 64x32 (8 warps: 2 along M x 4 along N). 2 CTAs/SM for latency hiding.
// revM: reverse m-tile order (LPT schedule for causal-K truncated GEMM).
// ---------------------------------------------------------------------------
__global__ __launch_bounds__(256, 2) void gemm_f16(
    const __half* __restrict__ A, const __half* __restrict__ B,
    float* __restrict__ outF, __half* __restrict__ outH,
    int lda, int ldb, int ldc, long sA, long sB, long sC,
    float alpha, int Ktot, int causalSkip, int causalK, int revM)
{
    const int mTile = revM ? (int)(gridDim.y - 1 - blockIdx.y) : (int)blockIdx.y;
    const int m0 = mTile * BM;
    const int n0 = blockIdx.x * BN;
    if (causalSkip && n0 >= m0 + BM) return;

    extern __shared__ char smem[];
    const uint32_t sb = smem_u32(smem);

    const int tid  = threadIdx.x;
    const int lane = tid & 31;
    const int wid  = tid >> 5;
    const int warpM0 = (wid >> 2) * 64;   // 2 warps along M
    const int warpN0 = (wid & 3) * 32;    // 4 warps along N

    A += (size_t)blockIdx.z * sA;
    B += (size_t)blockIdx.z * sB;

    const int kEnd = causalK ? min(Ktot, m0 + BM) : Ktot;
    const int nCh = kEnd / BK;

    auto issue = [&](int c) {
        const uint32_t st = sb + (uint32_t)(c & (STAGES - 1)) * STAGE_BYTES;
        const int k0 = c * BK;
#pragma unroll
        for (int r = 0; r < 2; r++) {
            const int i = tid + r * 256;
            const int row = i >> 2, c16 = i & 3;
            const uint32_t so = sw_off(row, c16);
            cp_async16(st + so,             A + (size_t)(m0 + row) * lda + k0 + c16 * 8);
            cp_async16(st + MAT_BYTES + so, B + (size_t)(n0 + row) * ldb + k0 + c16 * 8);
        }
    };

    float acc[4][4][4];
#pragma unroll
    for (int i = 0; i < 4; i++)
#pragma unroll
        for (int j = 0; j < 4; j++)
#pragma unroll
            for (int k = 0; k < 4; k++) acc[i][j][k] = 0.f;

    // prologue: 3 stages in flight
#pragma unroll
    for (int s = 0; s < STAGES - 1; s++) {
        if (s < nCh) issue(s);
        CP_COMMIT();
    }

    const int aRow = (lane & 15);
    const int aHi  = (lane >> 4);
    const int bRow = (lane & 7) + ((lane >> 4) << 3);   // B pair: nf / nf+1
    const int bHi  = ((lane >> 3) & 1);

    for (int c = 0; c < nCh; c++) {
        CP_WAIT2();
        __syncthreads();
        if (c + STAGES - 1 < nCh) issue(c + STAGES - 1);
        CP_COMMIT();

        const uint32_t st = sb + (uint32_t)(c & (STAGES - 1)) * STAGE_BYTES;
#pragma unroll
        for (int ks = 0; ks < 2; ks++) {
            uint32_t ah[4][4];
#pragma unroll
            for (int mf = 0; mf < 4; mf++) {
                const int row = warpM0 + mf * 16 + aRow;
                ldmx4(ah[mf][0], ah[mf][1], ah[mf][2], ah[mf][3],
                      st + sw_off(row, ks * 2 + aHi));
            }
#pragma unroll
            for (int nfp = 0; nfp < 2; nfp++) {
                const int row = warpN0 + nfp * 16 + bRow;
                uint32_t bh[4];
                ldmx4(bh[0], bh[1], bh[2], bh[3],
                      st + MAT_BYTES + sw_off(row, ks * 2 + bHi));
#pragma unroll
                for (int mf = 0; mf < 4; mf++) {
                    mma16816(acc[mf][2*nfp],     ah[mf], bh + 0);
                    mma16816(acc[mf][2*nfp + 1], ah[mf], bh + 2);
                }
            }
        }
    }

    // epilogue
    const long cb = (long)blockIdx.z * sC;
    const int rBase = m0 + warpM0 + (lane >> 2);
    const int cBase = n0 + warpN0 + (lane & 3) * 2;
#pragma unroll
    for (int mf = 0; mf < 4; mf++) {
#pragma unroll
        for (int nf = 0; nf < 4; nf++) {
            const int col = cBase + nf * 8;
#pragma unroll
            for (int h = 0; h < 2; h++) {
                const int row = rBase + mf * 16 + h * 8;
                const float v0 = acc[mf][nf][2 * h] * alpha;
                const float v1 = acc[mf][nf][2 * h + 1] * alpha;
                if (outF) {
                    *(float2*)(outF + cb + (size_t)row * ldc + col) =
                        make_float2(v0, v1);
                } else {
                    *(__half2*)(outH + cb + (size_t)row * ldc + col) =
                        __floats2half2_rn(v0, v1);
                }
            }
        }
    }
}

// ---------------------------------------------------------------------------
// One fused fp32->fp16 convert for x, Wq, Wk, Wv.
// ---------------------------------------------------------------------------
#define XN4 (BATCH*SEQ*DM/4)
#define WN4 (DM*DM/4)
__global__ __launch_bounds__(256) void to_f16_all(
    const float* __restrict__ x, const float* __restrict__ Wq,
    const float* __restrict__ Wk, const float* __restrict__ Wv,
    __half* __restrict__ x16, __half* __restrict__ W16)
{
    int i = blockIdx.x * 256 + threadIdx.x;
    const float* src;
    __half* dst;
    int off;
    if (i < XN4) { src = x; dst = x16; off = i; }
    else {
        int j = i - XN4;
        int w = j / WN4;
        off = j - w * WN4;
        src = (w == 0) ? Wq : (w == 1) ? Wk : Wv;
        dst = W16 + (size_t)w * DM * DM;
        if (i >= XN4 + 3 * WN4) return;
    }
    float4 v = ((const float4*)src)[off];
    __half2* D = (__half2*)dst + 2 * (size_t)off;
    D[0] = __floats2half2_rn(v.x, v.y);
    D[1] = __floats2half2_rn(v.z, v.w);
}

// src [B][SEQ][DM] -> dst [B][DM][SEQ]
__global__ __launch_bounds__(256) void transpose_f16(
    const __half* __restrict__ src, __half* __restrict__ dst)
{
    __shared__ __half t[64][65];
    const int b  = blockIdx.z;
    const int n0 = blockIdx.x * 64;
    const int k0 = blockIdx.y * 64;
    const int tx = threadIdx.x & 31, ty = threadIdx.x >> 5;

    const __half* s = src + ((size_t)b * SEQ + k0) * DM + n0;
#pragma unroll
    for (int i = 0; i < 8; i++) {
        int r = ty + i * 8;
        __half2 v = *(const __half2*)(s + (size_t)r * DM + 2 * tx);
        t[r][2*tx] = __low2half(v); t[r][2*tx+1] = __high2half(v);
    }
    __syncthreads();
    __half* d = dst + ((size_t)b * DM + n0) * SEQ + k0;
#pragma unroll
    for (int i = 0; i < 8; i++) {
        int rn = ty + i * 8;
        *(__half2*)(d + (size_t)rn * SEQ + 2 * tx) =
            __halves2half2(t[2*tx][rn], t[2*tx+1][rn]);
    }
}

// Causal softmax, in place on fp16 P. Reads k <= q only; zero-fills (q, 128-boundary).
__global__ __launch_bounds__(256) void softmax_causal(__half* __restrict__ P16)
{
    const int q = blockIdx.x, b = blockIdx.y;
    __half* row = P16 + ((size_t)b * SEQ + q) * SEQ;
    const int len = q + 1, tid = threadIdx.x;

    __shared__ float sred[8];
    __shared__ float sbc;

    float vals[8]; int n = 0;
    float m = -CUDART_INF_F;
    for (int i = tid; i < len; i += 256) {
        float v = __half2float(row[i]);
        vals[n++] = v;
        m = fmaxf(m, v);
    }
#pragma unroll
    for (int o = 16; o; o >>= 1) m = fmaxf(m, __shfl_xor_sync(0xffffffffu, m, o));
    if ((tid & 31) == 0) sred[tid >> 5] = m;
    __syncthreads();
    if (tid == 0) {
        float t = sred[0];
#pragma unroll
        for (int w = 1; w < 8; w++) t = fmaxf(t, sred[w]);
        sbc = t;
    }
    __syncthreads();
    m = sbc;

    float s = 0.f;
#pragma unroll
    for (int k = 0; k < 8; k++)
        if (k < n) { float e = expf(vals[k] - m); vals[k] = e; s += e; }
#pragma unroll
    for (int o = 16; o; o >>= 1) s += __shfl_xor_sync(0xffffffffu, s, o);
    __syncthreads();
    if ((tid & 31) == 0) sred[tid >> 5] = s;
    __syncthreads();
    if (tid == 0) {
        float t = 0.f;
#pragma unroll
        for (int w = 0; w < 8; w++) t += sred[w];
        sbc = 1.f / t;
    }
    __syncthreads();
    const float inv = sbc;

    n = 0;
    for (int i = tid; i < len; i += 256) row[i] = __float2half_rn(vals[n++] * inv);

    const __half z = __float2half_rn(0.f);
    const int tileEnd = ((q >> 7) + 1) << 7;
    for (int i = len + tid; i < tileEnd; i += 256) row[i] = z;
}

// ---------------------------------------------------------------------------
extern "C" void kernel_launch(void* const* d_in, const int* in_sizes, int n_in,
                              void* d_out, int out_size)
{
    const float* x  = (const float*)d_in[0];
    const float* Wq = (const float*)d_in[1];
    const float* Wk = (const float*)d_in[2];
    const float* Wv = (const float*)d_in[3];
    float* out = (float*)d_out;

    __half *x16, *W16, *QKV16, *Vt16, *P16;
    cudaGetSymbolAddress((void**)&x16, g_x16);
    cudaGetSymbolAddress((void**)&W16, g_W16);
    cudaGetSymbolAddress((void**)&QKV16, g_QKV16);
    cudaGetSymbolAddress((void**)&Vt16, g_Vt16);
    cudaGetSymbolAddress((void**)&P16, g_P16);

    const long BSD = (long)BATCH * SEQ * DM;
    const long SD  = (long)SEQ * DM;
    const long SS  = (long)SEQ * SEQ;

    cudaFuncSetAttribute(gemm_f16, cudaFuncAttributeMaxDynamicSharedMemorySize, SMEM_TOTAL);

    // 1) fused fp32 -> fp16 conversion (x + Wq + Wk + Wv)
    {
        const int total = XN4 + 3 * WN4;
        to_f16_all<<<(total + 255) / 256, 256>>>(x, Wq, Wk, Wv, x16, W16);
    }

    // 2) Fused QKV projection (z selects weight + output section; A fixed)
    {
        dim3 g(DM / BN, (BATCH * SEQ) / BM, 3);
        gemm_f16<<<g, 256, SMEM_TOTAL>>>(x16, W16,
            nullptr, QKV16,
            DM, DM, DM, 0, (long)DM * DM, BSD,
            1.f, DM, 0, 0, 0);
    }

    // 3) V transpose: [B][S][DM] -> [B][DM][S]
    {
        dim3 g(DM / 64, SEQ / 64, BATCH);
        transpose_f16<<<g, 256>>>(QKV16 + 2 * BSD, Vt16);
    }

    // 4) Scores -> fp16 P directly: P = (1/32) Q @ K^T (causal tile skip)
    {
        dim3 g(SEQ / BN, SEQ / BM, BATCH);
        gemm_f16<<<g, 256, SMEM_TOTAL>>>(QKV16, QKV16 + BSD,
            nullptr, P16,
            DM, DM, SEQ, SD, SD, SS,
            0.03125f, DM, 1, 0, 0);
    }

    // 5) Causal softmax in place on fp16 P (+ zero fill to 128-boundary)
    softmax_causal<<<dim3(SEQ, BATCH), 256>>>(P16);

    // 6) O = P @ V (K truncated at diagonal; longest m-tiles issued FIRST)
    {
        dim3 g(DM / BN, SEQ / BM, BATCH);
        gemm_f16<<<g, 256, SMEM_TOTAL>>>(P16, Vt16,
            out, nullptr,
            SEQ, SEQ, DM, SS, SD, SD,
            1.f, SEQ, 0, 1, 1);
    }
}